// round 1
// baseline (speedup 1.0000x reference)
#include <cuda_runtime.h>
#include <cuda_fp16.h>
#include <math.h>

#define BB 4
#define LL 5
#define TT 10
#define CC 64
#define HH 100
#define WW 352
#define NN (BB*LL)
#define HW (HH*WW)
#define H4 25
#define W4 88
#define P4 (H4*W4)

// scratch (no allocations allowed)
__device__ float g_tm4[NN*P4];
__device__ float g_has[NN];
__device__ float g_cmap[NN*HW];
__device__ unsigned char g_mask[NN*HW];

// 5x5 gaussian, sigma=1, normalized by 1/(2*pi*sigma): values by s=dy^2+dx^2
__constant__ float c_G[25] = {
    // dy=-2: s = 8,5,4,5,8
    0.0029150244947655228f, 0.013064233284684921f, 0.021539279301848634f, 0.013064233284684921f, 0.0029150244947655228f,
    // dy=-1: s = 5,2,1,2,5
    0.013064233284684921f, 0.05854983152431917f, 0.09653235263005391f, 0.05854983152431917f, 0.013064233284684921f,
    // dy=0: s = 4,1,0,1,4
    0.021539279301848634f, 0.09653235263005391f, 0.15915494309189535f, 0.09653235263005391f, 0.021539279301848634f,
    // dy=1
    0.013064233284684921f, 0.05854983152431917f, 0.09653235263005391f, 0.05854983152431917f, 0.013064233284684921f,
    // dy=2
    0.0029150244947655228f, 0.013064233284684921f, 0.021539279301848634f, 0.013064233284684921f, 0.0029150244947655228f
};

// ---------------- K1: per-agent trajectory mask at H4 x W4 ----------------
__global__ void k_traj(const float* __restrict__ traj_all,
                       const float* __restrict__ W1, const float* __restrict__ b1,
                       const float* __restrict__ W2, const float* __restrict__ b2,
                       const float* __restrict__ Wc1, const float* __restrict__ bc1,
                       const float* __restrict__ Wc2, const float* __restrict__ bc2)
{
    int n = blockIdx.x;
    int tid = threadIdx.x;
    __shared__ float s_tr[TT*3];
    __shared__ float s_h[64];
    __shared__ float s_f[128];
    __shared__ float s_rel[9*64];
    __shared__ float s_a9[9];
    __shared__ int   s_xi[TT], s_yi[TT];
    __shared__ float s_m[P4];
    __shared__ float s_part[256];

    if (tid < TT*3) s_tr[tid] = traj_all[n*TT*3 + tid];
    __syncthreads();

    if (tid == 0) {
        int h = 0;
        for (int i = 0; i < TT*3; i++) if (s_tr[i] != 0.0f) h = 1;
        g_has[n] = (float)h;
    }
    if (tid < TT) {
        float px = s_tr[tid*3+0] / 0.4f;     // DISCRETE_RATIO
        float py = s_tr[tid*3+1] / 0.4f;
        int xi = (int)(px / 4.0f);           // truncation like .astype(int32)
        int yi = (int)(py / 4.0f);
        xi = min(max(xi, 0), W4-1);
        yi = min(max(yi, 0), H4-1);
        s_xi[tid] = xi; s_yi[tid] = yi;
    }
    // hbar = mean_t relu(traj @ W1 + b1)
    if (tid < 64) {
        float acc = 0.0f;
        for (int t = 0; t < TT; t++) {
            float z = b1[tid];
            z += s_tr[t*3+0]*W1[0*64+tid];
            z += s_tr[t*3+1]*W1[1*64+tid];
            z += s_tr[t*3+2]*W1[2*64+tid];
            acc += fmaxf(z, 0.0f);
        }
        s_h[tid] = acc * 0.1f;
    }
    __syncthreads();
    // f = hbar @ W2 + b2
    if (tid < 128) {
        float z = b2[tid];
        for (int c = 0; c < 64; c++) z += s_h[c]*W2[c*128+tid];
        s_f[tid] = z;
    }
    __syncthreads();
    // conv3x3 on spatially constant feature -> 9 border cases per channel
    if (tid < 64) {
        float a9[9];
        #pragma unroll
        for (int q = 0; q < 9; q++) a9[q] = bc1[tid];
        const float* wp = Wc1 + (size_t)tid*128*9;
        for (int k = 0; k < 128; k++) {
            float fk = s_f[k];
            const float* w = wp + k*9;
            float w00=w[0], w01=w[1], w02=w[2];
            float w10=w[3], w11=w[4], w12=w[5];
            float w20=w[6], w21=w[7], w22=w[8];
            // per-kernel-row column sums: full, left edge (j=0: drop kw=0), right edge (drop kw=2)
            float rF0=w00+w01+w02, rL0=w01+w02, rR0=w00+w01;
            float rF1=w10+w11+w12, rL1=w11+w12, rR1=w10+w11;
            float rF2=w20+w21+w22, rL2=w21+w22, rR2=w20+w21;
            // row cases: top i=0 drops kh=0; bottom i=H4-1 drops kh=2
            a9[0] += fk*(rL1+rL2); a9[1] += fk*(rF1+rF2); a9[2] += fk*(rR1+rR2);
            a9[3] += fk*(rL0+rL1+rL2); a9[4] += fk*(rF0+rF1+rF2); a9[5] += fk*(rR0+rR1+rR2);
            a9[6] += fk*(rL0+rL1); a9[7] += fk*(rF0+rF1); a9[8] += fk*(rR0+rR1);
        }
        #pragma unroll
        for (int q = 0; q < 9; q++) s_rel[q*64+tid] = fmaxf(a9[q], 0.0f);
    }
    __syncthreads();
    if (tid < 9) {
        float z = bc2[0];
        for (int c = 0; c < 64; c++) z += Wc2[c]*s_rel[tid*64+c];
        s_a9[tid] = 1.0f/(1.0f+expf(-z));
    }
    // gaussian splat
    float lsum = 0.0f;
    for (int p = tid; p < P4; p += 256) {
        int i = p / W4, j = p % W4;
        float m = 0.0f;
        #pragma unroll
        for (int t = 0; t < TT; t++) {
            int di = i - s_yi[t], dj = j - s_xi[t];
            if (di >= -3 && di <= 3 && dj >= -3 && dj <= 3)
                m += expf(-(float)(di*di+dj*dj)*0.125f);  // 2*sigma^2 = 8
        }
        s_m[p] = m; lsum += m;
    }
    s_part[tid] = lsum;
    __syncthreads();
    for (int off = 128; off > 0; off >>= 1) {
        if (tid < off) s_part[tid] += s_part[tid+off];
        __syncthreads();
    }
    float inv = 1.0f / fmaxf(s_part[0], 1e-12f);
    for (int p = tid; p < P4; p += 256) {
        int i = p / W4, j = p % W4;
        int r  = (i == 0) ? 0 : ((i == H4-1) ? 2 : 1);
        int cc = (j == 0) ? 0 : ((j == W4-1) ? 2 : 1);
        g_tm4[n*P4 + p] = s_m[p]*inv*s_a9[r*3+cc];
    }
}

// ---------------- K2: upsample + modify conf + sigmoid + max over A ----------------
__global__ void k_cmap(const float* __restrict__ psm)
{
    int idx = blockIdx.x*blockDim.x + threadIdx.x;
    if (idx >= NN*HW) return;
    int n = idx / HW, p = idx % HW;
    int h = p / WW, w = p % WW;
    float uy = fminf(fmaxf((h+0.5f)*0.25f - 0.5f, 0.0f), (float)(H4-1));
    float ux = fminf(fmaxf((w+0.5f)*0.25f - 0.5f, 0.0f), (float)(W4-1));
    int y0 = (int)uy, x0 = (int)ux;
    float fy = uy - y0, fx = ux - x0;
    int y1 = min(y0+1, H4-1), x1 = min(x0+1, W4-1);
    const float* t = g_tm4 + n*P4;
    float v00 = t[y0*W4+x0], v01 = t[y0*W4+x1];
    float v10 = t[y1*W4+x0], v11 = t[y1*W4+x1];
    float tm = v00*(1.0f-fy)*(1.0f-fx) + v01*(1.0f-fy)*fx
             + v10*fy*(1.0f-fx)        + v11*fy*fx;
    float fac = 1.0f + g_has[n]*tm;
    float a0 = psm[(size_t)(n*2+0)*HW + p]*fac;
    float a1 = psm[(size_t)(n*2+1)*HW + p]*fac;
    float c0 = 1.0f/(1.0f+expf(-a0));
    float c1 = 1.0f/(1.0f+expf(-a1));
    g_cmap[idx] = fmaxf(c0, c1);
}

// ---------------- K3: 5x5 gaussian smooth + threshold + ego force ----------------
__global__ void k_mask()
{
    int idx = blockIdx.x*blockDim.x + threadIdx.x;
    if (idx >= NN*HW) return;
    int n = idx / HW, p = idx % HW;
    int h = p / WW, w = p % WW;
    const float* cm = g_cmap + (size_t)n*HW;
    float acc = 0.0f;
    #pragma unroll
    for (int dy = -2; dy <= 2; dy++) {
        int hh = h + dy;
        if (hh < 0 || hh >= HH) continue;
        #pragma unroll
        for (int dx = -2; dx <= 2; dx++) {
            int ww2 = w + dx;
            if (ww2 < 0 || ww2 >= WW) continue;
            acc += c_G[(dy+2)*5 + (dx+2)] * cm[hh*WW + ww2];
        }
    }
    int l = n % LL;
    g_mask[idx] = (l == 0) ? 1 : ((acc > 0.01f) ? 1 : 0);
}

// ---------------- K4: masked ego-row attention fusion ----------------
__global__ void __launch_bounds__(256, 1)
k_fuse(const float* __restrict__ x, float* __restrict__ out)
{
    extern __shared__ __half sv[];   // [5][64][256], tid fastest
    int p = blockIdx.x*blockDim.x + threadIdx.x;
    if (p >= HW) return;
    int b = blockIdx.y;
    int tid = threadIdx.x;

    const float* xb = x + (size_t)b*LL*CC*HW + p;
    float mk[LL];
    #pragma unroll
    for (int m = 0; m < LL; m++)
        mk[m] = (float)g_mask[(size_t)(b*LL+m)*HW + p];

    float d0=0.f, d1=0.f, d2=0.f, d3=0.f, d4=0.f;
    #pragma unroll 4
    for (int c = 0; c < CC; c++) {
        float v0 = xb[(size_t)(0*CC+c)*HW] * mk[0];
        float v1 = xb[(size_t)(1*CC+c)*HW] * mk[1];
        float v2 = xb[(size_t)(2*CC+c)*HW] * mk[2];
        float v3 = xb[(size_t)(3*CC+c)*HW] * mk[3];
        float v4 = xb[(size_t)(4*CC+c)*HW] * mk[4];
        sv[(0*CC+c)*256 + tid] = __float2half(v0);
        sv[(1*CC+c)*256 + tid] = __float2half(v1);
        sv[(2*CC+c)*256 + tid] = __float2half(v2);
        sv[(3*CC+c)*256 + tid] = __float2half(v3);
        sv[(4*CC+c)*256 + tid] = __float2half(v4);
        d0 += v0*v0; d1 += v0*v1; d2 += v0*v2; d3 += v0*v3; d4 += v0*v4;
    }
    const float scale = 0.125f;  // 1/sqrt(64)
    float s0 = d0*scale, s1 = d1*scale, s2 = d2*scale, s3 = d3*scale, s4 = d4*scale;
    float mx = fmaxf(fmaxf(fmaxf(s0, s1), fmaxf(s2, s3)), s4);
    float e0 = expf(s0-mx), e1 = expf(s1-mx), e2 = expf(s2-mx), e3 = expf(s3-mx), e4 = expf(s4-mx);
    float isum = 1.0f/(e0+e1+e2+e3+e4);
    float w0 = e0*isum, w1 = e1*isum, w2 = e2*isum, w3 = e3*isum, w4 = e4*isum;

    float* ob = out + (size_t)b*CC*HW + p;
    #pragma unroll 4
    for (int c = 0; c < CC; c++) {
        float acc = w0*__half2float(sv[(0*CC+c)*256 + tid])
                  + w1*__half2float(sv[(1*CC+c)*256 + tid])
                  + w2*__half2float(sv[(2*CC+c)*256 + tid])
                  + w3*__half2float(sv[(3*CC+c)*256 + tid])
                  + w4*__half2float(sv[(4*CC+c)*256 + tid]);
        ob[(size_t)c*HW] = acc;
    }
}

extern "C" void kernel_launch(void* const* d_in, const int* in_sizes, int n_in,
                              void* d_out, int out_size)
{
    const float* x    = (const float*)d_in[0];
    const float* psm  = (const float*)d_in[1];
    // d_in[2] record_len, d_in[3] pairwise_t_matrix: unused by reference
    const float* traj = (const float*)d_in[4];
    const float* W1   = (const float*)d_in[5];
    const float* b1   = (const float*)d_in[6];
    const float* W2   = (const float*)d_in[7];
    const float* b2   = (const float*)d_in[8];
    const float* Wc1  = (const float*)d_in[9];
    const float* bc1  = (const float*)d_in[10];
    const float* Wc2  = (const float*)d_in[11];
    const float* bc2  = (const float*)d_in[12];
    float* out = (float*)d_out;

    const int fuse_smem = LL*CC*256*(int)sizeof(__half);   // 163840 B
    cudaFuncSetAttribute((const void*)k_fuse,
                         cudaFuncAttributeMaxDynamicSharedMemorySize, fuse_smem);

    k_traj<<<NN, 256>>>(traj, W1, b1, W2, b2, Wc1, bc1, Wc2, bc2);
    int tot = NN*HW;
    k_cmap<<<(tot+255)/256, 256>>>(psm);
    k_mask<<<(tot+255)/256, 256>>>();
    dim3 g((HW+255)/256, BB);
    k_fuse<<<g, 256, fuse_smem>>>(x, out);
}

// round 2
// speedup vs baseline: 1.9188x; 1.9188x over previous
#include <cuda_runtime.h>
#include <math.h>

#define BB 4
#define LL 5
#define TT 10
#define CC 64
#define HH 100
#define WW 352
#define NN (BB*LL)
#define HW (HH*WW)
#define H4 25
#define W4 88
#define P4 (H4*W4)

// scratch (no allocations allowed)
__device__ float g_tm4[NN*P4];
__device__ float g_has[NN];
__device__ float g_cmap[NN*HW];
__device__ unsigned char g_mask[NN*HW];

// 5x5 gaussian, sigma=1, normalized by 1/(2*pi*sigma): values by s=dy^2+dx^2
__constant__ float c_G[25] = {
    0.0029150244947655228f, 0.013064233284684921f, 0.021539279301848634f, 0.013064233284684921f, 0.0029150244947655228f,
    0.013064233284684921f, 0.05854983152431917f, 0.09653235263005391f, 0.05854983152431917f, 0.013064233284684921f,
    0.021539279301848634f, 0.09653235263005391f, 0.15915494309189535f, 0.09653235263005391f, 0.021539279301848634f,
    0.013064233284684921f, 0.05854983152431917f, 0.09653235263005391f, 0.05854983152431917f, 0.013064233284684921f,
    0.0029150244947655228f, 0.013064233284684921f, 0.021539279301848634f, 0.013064233284684921f, 0.0029150244947655228f
};

// ---------------- K1: per-agent trajectory mask at H4 x W4 ----------------
__global__ void k_traj(const float* __restrict__ traj_all,
                       const float* __restrict__ W1, const float* __restrict__ b1,
                       const float* __restrict__ W2, const float* __restrict__ b2,
                       const float* __restrict__ Wc1, const float* __restrict__ bc1,
                       const float* __restrict__ Wc2, const float* __restrict__ bc2)
{
    int n = blockIdx.x;
    int tid = threadIdx.x;
    __shared__ float s_tr[TT*3];
    __shared__ float s_h[64];
    __shared__ float s_f[128];
    __shared__ float s_pc[4][9][64];   // conv partials per k-chunk
    __shared__ float s_rel[9*64];
    __shared__ float s_a9[9];
    __shared__ int   s_xi[TT], s_yi[TT];
    __shared__ float s_m[P4];
    __shared__ float s_part[256];

    if (tid < TT*3) s_tr[tid] = traj_all[n*TT*3 + tid];
    __syncthreads();

    if (tid == 0) {
        int h = 0;
        for (int i = 0; i < TT*3; i++) if (s_tr[i] != 0.0f) h = 1;
        g_has[n] = (float)h;
    }
    if (tid < TT) {
        float px = s_tr[tid*3+0] / 0.4f;     // DISCRETE_RATIO
        float py = s_tr[tid*3+1] / 0.4f;
        int xi = (int)(px / 4.0f);           // truncation like .astype(int32)
        int yi = (int)(py / 4.0f);
        xi = min(max(xi, 0), W4-1);
        yi = min(max(yi, 0), H4-1);
        s_xi[tid] = xi; s_yi[tid] = yi;
    }
    // hbar = mean_t relu(traj @ W1 + b1)
    if (tid < 64) {
        float acc = 0.0f;
        for (int t = 0; t < TT; t++) {
            float z = b1[tid];
            z += s_tr[t*3+0]*W1[0*64+tid];
            z += s_tr[t*3+1]*W1[1*64+tid];
            z += s_tr[t*3+2]*W1[2*64+tid];
            acc += fmaxf(z, 0.0f);
        }
        s_h[tid] = acc * 0.1f;
    }
    __syncthreads();
    // f = hbar @ W2 + b2
    if (tid < 128) {
        float z = b2[tid];
        for (int c = 0; c < 64; c++) z += s_h[c]*W2[c*128+tid];
        s_f[tid] = z;
    }
    __syncthreads();
    // conv3x3 on spatially constant feature -> 9 border cases per channel
    // 256 threads = 64 output channels x 4 k-chunks (32 k's each)
    {
        int o  = tid & 63;
        int kg = tid >> 6;
        float a9[9];
        #pragma unroll
        for (int q = 0; q < 9; q++) a9[q] = 0.0f;
        const float* wp = Wc1 + (size_t)o*128*9 + (size_t)kg*32*9;
        #pragma unroll 4
        for (int k = 0; k < 32; k++) {
            float fk = s_f[kg*32 + k];
            const float* w = wp + k*9;
            float w00=w[0], w01=w[1], w02=w[2];
            float w10=w[3], w11=w[4], w12=w[5];
            float w20=w[6], w21=w[7], w22=w[8];
            float rF0=w00+w01+w02, rL0=w01+w02, rR0=w00+w01;
            float rF1=w10+w11+w12, rL1=w11+w12, rR1=w10+w11;
            float rF2=w20+w21+w22, rL2=w21+w22, rR2=w20+w21;
            a9[0] += fk*(rL1+rL2); a9[1] += fk*(rF1+rF2); a9[2] += fk*(rR1+rR2);
            a9[3] += fk*(rL0+rL1+rL2); a9[4] += fk*(rF0+rF1+rF2); a9[5] += fk*(rR0+rR1+rR2);
            a9[6] += fk*(rL0+rL1); a9[7] += fk*(rF0+rF1); a9[8] += fk*(rR0+rR1);
        }
        #pragma unroll
        for (int q = 0; q < 9; q++) s_pc[kg][q][o] = a9[q];
    }
    __syncthreads();
    if (tid < 64) {
        #pragma unroll
        for (int q = 0; q < 9; q++) {
            float z = bc1[tid] + s_pc[0][q][tid] + s_pc[1][q][tid]
                               + s_pc[2][q][tid] + s_pc[3][q][tid];
            s_rel[q*64+tid] = fmaxf(z, 0.0f);
        }
    }
    __syncthreads();
    if (tid < 9) {
        float z = bc2[0];
        for (int c = 0; c < 64; c++) z += Wc2[c]*s_rel[tid*64+c];
        s_a9[tid] = 1.0f/(1.0f+expf(-z));
    }
    // gaussian splat
    float lsum = 0.0f;
    for (int p = tid; p < P4; p += 256) {
        int i = p / W4, j = p % W4;
        float m = 0.0f;
        #pragma unroll
        for (int t = 0; t < TT; t++) {
            int di = i - s_yi[t], dj = j - s_xi[t];
            if (di >= -3 && di <= 3 && dj >= -3 && dj <= 3)
                m += expf(-(float)(di*di+dj*dj)*0.125f);  // 2*sigma^2 = 8
        }
        s_m[p] = m; lsum += m;
    }
    s_part[tid] = lsum;
    __syncthreads();
    for (int off = 128; off > 0; off >>= 1) {
        if (tid < off) s_part[tid] += s_part[tid+off];
        __syncthreads();
    }
    float inv = 1.0f / fmaxf(s_part[0], 1e-12f);
    for (int p = tid; p < P4; p += 256) {
        int i = p / W4, j = p % W4;
        int r  = (i == 0) ? 0 : ((i == H4-1) ? 2 : 1);
        int cc = (j == 0) ? 0 : ((j == W4-1) ? 2 : 1);
        g_tm4[n*P4 + p] = s_m[p]*inv*s_a9[r*3+cc];
    }
}

// ---------------- K2: upsample + modify conf + sigmoid + max over A ----------------
__global__ void k_cmap(const float* __restrict__ psm)
{
    int idx = blockIdx.x*blockDim.x + threadIdx.x;
    if (idx >= NN*HW) return;
    int n = idx / HW, p = idx % HW;
    int h = p / WW, w = p % WW;
    float uy = fminf(fmaxf((h+0.5f)*0.25f - 0.5f, 0.0f), (float)(H4-1));
    float ux = fminf(fmaxf((w+0.5f)*0.25f - 0.5f, 0.0f), (float)(W4-1));
    int y0 = (int)uy, x0 = (int)ux;
    float fy = uy - y0, fx = ux - x0;
    int y1 = min(y0+1, H4-1), x1 = min(x0+1, W4-1);
    const float* t = g_tm4 + n*P4;
    float v00 = t[y0*W4+x0], v01 = t[y0*W4+x1];
    float v10 = t[y1*W4+x0], v11 = t[y1*W4+x1];
    float tm = v00*(1.0f-fy)*(1.0f-fx) + v01*(1.0f-fy)*fx
             + v10*fy*(1.0f-fx)        + v11*fy*fx;
    float fac = 1.0f + g_has[n]*tm;
    float a0 = psm[(size_t)(n*2+0)*HW + p]*fac;
    float a1 = psm[(size_t)(n*2+1)*HW + p]*fac;
    float c0 = 1.0f/(1.0f+expf(-a0));
    float c1 = 1.0f/(1.0f+expf(-a1));
    g_cmap[idx] = fmaxf(c0, c1);
}

// ---------------- K3: 5x5 gaussian smooth + threshold + ego force ----------------
__global__ void k_mask()
{
    int idx = blockIdx.x*blockDim.x + threadIdx.x;
    if (idx >= NN*HW) return;
    int n = idx / HW, p = idx % HW;
    int h = p / WW, w = p % WW;
    const float* cm = g_cmap + (size_t)n*HW;
    float acc = 0.0f;
    #pragma unroll
    for (int dy = -2; dy <= 2; dy++) {
        int hh = h + dy;
        if (hh < 0 || hh >= HH) continue;
        #pragma unroll
        for (int dx = -2; dx <= 2; dx++) {
            int ww2 = w + dx;
            if (ww2 < 0 || ww2 >= WW) continue;
            acc += c_G[(dy+2)*5 + (dx+2)] * cm[hh*WW + ww2];
        }
    }
    int l = n % LL;
    g_mask[idx] = (l == 0) ? 1 : ((acc > 0.01f) ? 1 : 0);
}

// ---------------- K4: masked ego-row attention fusion (register-resident) ----------------
// Block = 32 pixels x 8 channel-groups. Each thread holds 5 agents x 8 channels in regs.
__global__ void __launch_bounds__(256)
k_fuse(const float* __restrict__ x, float* __restrict__ out)
{
    __shared__ float s_d[8][5][32];
    __shared__ float s_w[5][32];

    int px = threadIdx.x & 31;
    int cg = threadIdx.x >> 5;        // 0..7
    int p  = blockIdx.x * 32 + px;    // HW = 35200 = 1100 * 32, always in range
    int b  = blockIdx.y;

    const float* xb = x + (size_t)b*LL*CC*HW + p;

    float mk[LL];
    #pragma unroll
    for (int m = 0; m < LL; m++)
        mk[m] = (float)g_mask[(size_t)(b*LL+m)*HW + p];

    // load 5 agents x 8 channels into registers (x read exactly once)
    float v[LL][8];
    #pragma unroll
    for (int m = 0; m < LL; m++) {
        #pragma unroll
        for (int i = 0; i < 8; i++)
            v[m][i] = xb[(size_t)(m*CC + cg*8 + i)*HW] * mk[m];
    }

    // partial ego-row dot products over this thread's 8 channels
    float d[LL];
    #pragma unroll
    for (int m = 0; m < LL; m++) d[m] = 0.0f;
    #pragma unroll
    for (int i = 0; i < 8; i++) {
        #pragma unroll
        for (int m = 0; m < LL; m++) d[m] += v[0][i]*v[m][i];
    }
    #pragma unroll
    for (int m = 0; m < LL; m++) s_d[cg][m][px] = d[m];
    __syncthreads();

    if (cg == 0) {   // warp 0 finishes dots + softmax
        float s[LL];
        #pragma unroll
        for (int m = 0; m < LL; m++) {
            float acc = 0.0f;
            #pragma unroll
            for (int g = 0; g < 8; g++) acc += s_d[g][m][px];
            s[m] = acc * 0.125f;   // 1/sqrt(64)
        }
        float mx = fmaxf(fmaxf(fmaxf(s[0], s[1]), fmaxf(s[2], s[3])), s[4]);
        float e[LL], sum = 0.0f;
        #pragma unroll
        for (int m = 0; m < LL; m++) { e[m] = expf(s[m]-mx); sum += e[m]; }
        float isum = 1.0f/sum;
        #pragma unroll
        for (int m = 0; m < LL; m++) s_w[m][px] = e[m]*isum;
    }
    __syncthreads();

    float w[LL];
    #pragma unroll
    for (int m = 0; m < LL; m++) w[m] = s_w[m][px];

    float* ob = out + (size_t)b*CC*HW + p;
    #pragma unroll
    for (int i = 0; i < 8; i++) {
        float acc = w[0]*v[0][i] + w[1]*v[1][i] + w[2]*v[2][i]
                  + w[3]*v[3][i] + w[4]*v[4][i];
        ob[(size_t)(cg*8+i)*HW] = acc;
    }
}

extern "C" void kernel_launch(void* const* d_in, const int* in_sizes, int n_in,
                              void* d_out, int out_size)
{
    const float* x    = (const float*)d_in[0];
    const float* psm  = (const float*)d_in[1];
    // d_in[2] record_len, d_in[3] pairwise_t_matrix: unused by reference
    const float* traj = (const float*)d_in[4];
    const float* W1   = (const float*)d_in[5];
    const float* b1   = (const float*)d_in[6];
    const float* W2   = (const float*)d_in[7];
    const float* b2   = (const float*)d_in[8];
    const float* Wc1  = (const float*)d_in[9];
    const float* bc1  = (const float*)d_in[10];
    const float* Wc2  = (const float*)d_in[11];
    const float* bc2  = (const float*)d_in[12];
    float* out = (float*)d_out;

    k_traj<<<NN, 256>>>(traj, W1, b1, W2, b2, Wc1, bc1, Wc2, bc2);
    int tot = NN*HW;
    k_cmap<<<(tot+255)/256, 256>>>(psm);
    k_mask<<<(tot+255)/256, 256>>>();
    dim3 g(HW/32, BB);
    k_fuse<<<g, 256>>>(x, out);
}

// round 3
// speedup vs baseline: 2.0199x; 1.0527x over previous
#include <cuda_runtime.h>
#include <math.h>

#define BB 4
#define LL 5
#define TT 10
#define CC 64
#define HH 100
#define WW 352
#define NN (BB*LL)
#define HW (HH*WW)
#define H4 25
#define W4 88
#define P4 (H4*W4)

// scratch (no allocations allowed)
__device__ float g_tm4[NN*P4];
__device__ float g_has[NN];
__device__ unsigned char g_mask[NN*HW];

// 5x5 gaussian, sigma=1, scaled by 1/(2*pi*sigma)
__constant__ float c_G[25] = {
    0.0029150244947655228f, 0.013064233284684921f, 0.021539279301848634f, 0.013064233284684921f, 0.0029150244947655228f,
    0.013064233284684921f, 0.05854983152431917f, 0.09653235263005391f, 0.05854983152431917f, 0.013064233284684921f,
    0.021539279301848634f, 0.09653235263005391f, 0.15915494309189535f, 0.09653235263005391f, 0.021539279301848634f,
    0.013064233284684921f, 0.05854983152431917f, 0.09653235263005391f, 0.05854983152431917f, 0.013064233284684921f,
    0.0029150244947655228f, 0.013064233284684921f, 0.021539279301848634f, 0.013064233284684921f, 0.0029150244947655228f
};

// ---------------- K1: per-agent trajectory mask at H4 x W4 ----------------
__global__ void __launch_bounds__(512)
k_traj(const float* __restrict__ traj_all,
       const float* __restrict__ W1, const float* __restrict__ b1,
       const float* __restrict__ W2, const float* __restrict__ b2,
       const float* __restrict__ Wc1, const float* __restrict__ bc1,
       const float* __restrict__ Wc2, const float* __restrict__ bc2)
{
    int n = blockIdx.x;
    int tid = threadIdx.x;
    __shared__ float s_tr[TT*3];
    __shared__ float s_h[64];
    __shared__ float s_f[128];
    __shared__ float s_pc[8][9][64];   // conv partials per k-chunk
    __shared__ float s_rel[9*64];
    __shared__ float s_a9[9];
    __shared__ int   s_xi[TT], s_yi[TT];
    __shared__ float s_m[P4];
    __shared__ float s_part[512];

    if (tid < TT*3) s_tr[tid] = traj_all[n*TT*3 + tid];
    __syncthreads();

    if (tid == 0) {
        int h = 0;
        for (int i = 0; i < TT*3; i++) if (s_tr[i] != 0.0f) h = 1;
        g_has[n] = (float)h;
    }
    if (tid < TT) {
        float px = s_tr[tid*3+0] / 0.4f;     // DISCRETE_RATIO
        float py = s_tr[tid*3+1] / 0.4f;
        int xi = (int)(px / 4.0f);           // truncation like .astype(int32)
        int yi = (int)(py / 4.0f);
        xi = min(max(xi, 0), W4-1);
        yi = min(max(yi, 0), H4-1);
        s_xi[tid] = xi; s_yi[tid] = yi;
    }
    // hbar = mean_t relu(traj @ W1 + b1)
    if (tid < 64) {
        float acc = 0.0f;
        for (int t = 0; t < TT; t++) {
            float z = b1[tid];
            z += s_tr[t*3+0]*W1[0*64+tid];
            z += s_tr[t*3+1]*W1[1*64+tid];
            z += s_tr[t*3+2]*W1[2*64+tid];
            acc += fmaxf(z, 0.0f);
        }
        s_h[tid] = acc * 0.1f;
    }
    __syncthreads();
    // f = hbar @ W2 + b2
    if (tid < 128) {
        float z = b2[tid];
        for (int c = 0; c < 64; c++) z += s_h[c]*W2[c*128+tid];
        s_f[tid] = z;
    }
    __syncthreads();
    // conv3x3 on spatially constant feature -> 9 border cases per channel
    // 512 threads = 64 output channels x 8 k-chunks (16 k's each)
    {
        int o  = tid & 63;
        int kg = tid >> 6;
        float a9[9];
        #pragma unroll
        for (int q = 0; q < 9; q++) a9[q] = 0.0f;
        const float* wp = Wc1 + (size_t)o*128*9 + (size_t)kg*16*9;
        #pragma unroll 4
        for (int k = 0; k < 16; k++) {
            float fk = s_f[kg*16 + k];
            const float* w = wp + k*9;
            float w00=w[0], w01=w[1], w02=w[2];
            float w10=w[3], w11=w[4], w12=w[5];
            float w20=w[6], w21=w[7], w22=w[8];
            float rF0=w00+w01+w02, rL0=w01+w02, rR0=w00+w01;
            float rF1=w10+w11+w12, rL1=w11+w12, rR1=w10+w11;
            float rF2=w20+w21+w22, rL2=w21+w22, rR2=w20+w21;
            a9[0] += fk*(rL1+rL2); a9[1] += fk*(rF1+rF2); a9[2] += fk*(rR1+rR2);
            a9[3] += fk*(rL0+rL1+rL2); a9[4] += fk*(rF0+rF1+rF2); a9[5] += fk*(rR0+rR1+rR2);
            a9[6] += fk*(rL0+rL1); a9[7] += fk*(rF0+rF1); a9[8] += fk*(rR0+rR1);
        }
        #pragma unroll
        for (int q = 0; q < 9; q++) s_pc[kg][q][o] = a9[q];
    }
    __syncthreads();
    if (tid < 64) {
        #pragma unroll
        for (int q = 0; q < 9; q++) {
            float z = bc1[tid];
            #pragma unroll
            for (int g = 0; g < 8; g++) z += s_pc[g][q][tid];
            s_rel[q*64+tid] = fmaxf(z, 0.0f);
        }
    }
    __syncthreads();
    if (tid < 9) {
        float z = bc2[0];
        for (int c = 0; c < 64; c++) z += Wc2[c]*s_rel[tid*64+c];
        s_a9[tid] = 1.0f/(1.0f+expf(-z));
    }
    // gaussian splat
    float lsum = 0.0f;
    for (int p = tid; p < P4; p += 512) {
        int i = p / W4, j = p % W4;
        float m = 0.0f;
        #pragma unroll
        for (int t = 0; t < TT; t++) {
            int di = i - s_yi[t], dj = j - s_xi[t];
            if (di >= -3 && di <= 3 && dj >= -3 && dj <= 3)
                m += expf(-(float)(di*di+dj*dj)*0.125f);  // 2*sigma^2 = 8
        }
        s_m[p] = m; lsum += m;
    }
    s_part[tid] = lsum;
    __syncthreads();
    for (int off = 256; off > 0; off >>= 1) {
        if (tid < off) s_part[tid] += s_part[tid+off];
        __syncthreads();
    }
    float inv = 1.0f / fmaxf(s_part[0], 1e-12f);
    for (int p = tid; p < P4; p += 512) {
        int i = p / W4, j = p % W4;
        int r  = (i == 0) ? 0 : ((i == H4-1) ? 2 : 1);
        int cc = (j == 0) ? 0 : ((j == W4-1) ? 2 : 1);
        g_tm4[n*P4 + p] = s_m[p]*inv*s_a9[r*3+cc];
    }
}

// ---------------- K2: fused cmap + 5x5 smooth + threshold + ego force ----------------
// Tile 32x8, halo 2 -> 36x12 cmap values computed in smem (zero outside = conv zero-pad).
__global__ void __launch_bounds__(256)
k_cmask(const float* __restrict__ psm)
{
    __shared__ float s_c[12][36];
    int n  = blockIdx.z;
    int bx = blockIdx.x * 32;
    int by = blockIdx.y * 8;
    int tid = threadIdx.x;

    const float* tmn = g_tm4 + n*P4;
    float has = g_has[n];

    for (int i = tid; i < 12*36; i += 256) {
        int ly = i / 36, lx = i - ly*36;
        int gx = bx + lx - 2, gy = by + ly - 2;
        float val = 0.0f;
        if (gx >= 0 && gx < WW && gy >= 0 && gy < HH) {
            float uy = fminf(fmaxf((gy+0.5f)*0.25f - 0.5f, 0.0f), (float)(H4-1));
            float ux = fminf(fmaxf((gx+0.5f)*0.25f - 0.5f, 0.0f), (float)(W4-1));
            int y0 = (int)uy, x0 = (int)ux;
            float fy = uy - y0, fx = ux - x0;
            int y1 = min(y0+1, H4-1), x1 = min(x0+1, W4-1);
            float v00 = tmn[y0*W4+x0], v01 = tmn[y0*W4+x1];
            float v10 = tmn[y1*W4+x0], v11 = tmn[y1*W4+x1];
            float tm = v00*(1.0f-fy)*(1.0f-fx) + v01*(1.0f-fy)*fx
                     + v10*fy*(1.0f-fx)        + v11*fy*fx;
            float fac = 1.0f + has*tm;
            int p = gy*WW + gx;
            float a0 = psm[(size_t)(n*2+0)*HW + p]*fac;
            float a1 = psm[(size_t)(n*2+1)*HW + p]*fac;
            float c0 = 1.0f/(1.0f+expf(-a0));
            float c1 = 1.0f/(1.0f+expf(-a1));
            val = fmaxf(c0, c1);
        }
        s_c[ly][lx] = val;
    }
    __syncthreads();

    int lx = tid & 31, ly = tid >> 5;
    int gx = bx + lx, gy = by + ly;
    if (gy < HH) {
        float acc = 0.0f;
        #pragma unroll
        for (int dy = 0; dy < 5; dy++) {
            #pragma unroll
            for (int dx = 0; dx < 5; dx++)
                acc += c_G[dy*5+dx] * s_c[ly+dy][lx+dx];
        }
        int l = n % LL;
        g_mask[(size_t)n*HW + gy*WW + gx] = (l == 0) ? 1 : ((acc > 0.01f) ? 1 : 0);
    }
}

// ---------------- K3: masked ego-row attention fusion (register-resident) ----------------
// Block = 32 pixels x 16 channel-groups (4 ch each). x read exactly once, all fp32.
__global__ void __launch_bounds__(512, 3)
k_fuse(const float* __restrict__ x, float* __restrict__ out)
{
    __shared__ float s_d[16][5][32];
    __shared__ float s_w[5][32];

    int px = threadIdx.x & 31;
    int cg = threadIdx.x >> 5;        // 0..15
    int p  = blockIdx.x * 32 + px;    // HW = 35200 = 1100 * 32
    int b  = blockIdx.y;

    const float* xb = x + (size_t)b*LL*CC*HW + p;

    float mk[LL];
    #pragma unroll
    for (int m = 0; m < LL; m++)
        mk[m] = (float)g_mask[(size_t)(b*LL+m)*HW + p];

    float v[LL][4];
    #pragma unroll
    for (int m = 0; m < LL; m++) {
        #pragma unroll
        for (int i = 0; i < 4; i++)
            v[m][i] = xb[(size_t)(m*CC + cg*4 + i)*HW] * mk[m];
    }

    float d[LL];
    #pragma unroll
    for (int m = 0; m < LL; m++) d[m] = 0.0f;
    #pragma unroll
    for (int i = 0; i < 4; i++) {
        #pragma unroll
        for (int m = 0; m < LL; m++) d[m] += v[0][i]*v[m][i];
    }
    #pragma unroll
    for (int m = 0; m < LL; m++) s_d[cg][m][px] = d[m];
    __syncthreads();

    if (cg == 0) {   // warp 0 finishes dots + softmax
        float s[LL];
        #pragma unroll
        for (int m = 0; m < LL; m++) {
            float acc = 0.0f;
            #pragma unroll
            for (int g = 0; g < 16; g++) acc += s_d[g][m][px];
            s[m] = acc * 0.125f;   // 1/sqrt(64)
        }
        float mx = fmaxf(fmaxf(fmaxf(s[0], s[1]), fmaxf(s[2], s[3])), s[4]);
        float e[LL], sum = 0.0f;
        #pragma unroll
        for (int m = 0; m < LL; m++) { e[m] = expf(s[m]-mx); sum += e[m]; }
        float isum = 1.0f/sum;
        #pragma unroll
        for (int m = 0; m < LL; m++) s_w[m][px] = e[m]*isum;
    }
    __syncthreads();

    float w[LL];
    #pragma unroll
    for (int m = 0; m < LL; m++) w[m] = s_w[m][px];

    float* ob = out + (size_t)b*CC*HW + p;
    #pragma unroll
    for (int i = 0; i < 4; i++) {
        float acc = w[0]*v[0][i] + w[1]*v[1][i] + w[2]*v[2][i]
                  + w[3]*v[3][i] + w[4]*v[4][i];
        ob[(size_t)(cg*4+i)*HW] = acc;
    }
}

extern "C" void kernel_launch(void* const* d_in, const int* in_sizes, int n_in,
                              void* d_out, int out_size)
{
    const float* x    = (const float*)d_in[0];
    const float* psm  = (const float*)d_in[1];
    // d_in[2] record_len, d_in[3] pairwise_t_matrix: unused by reference
    const float* traj = (const float*)d_in[4];
    const float* W1   = (const float*)d_in[5];
    const float* b1   = (const float*)d_in[6];
    const float* W2   = (const float*)d_in[7];
    const float* b2   = (const float*)d_in[8];
    const float* Wc1  = (const float*)d_in[9];
    const float* bc1  = (const float*)d_in[10];
    const float* Wc2  = (const float*)d_in[11];
    const float* bc2  = (const float*)d_in[12];
    float* out = (float*)d_out;

    k_traj<<<NN, 512>>>(traj, W1, b1, W2, b2, Wc1, bc1, Wc2, bc2);
    dim3 gm(WW/32, (HH+7)/8, NN);
    k_cmask<<<gm, 256>>>(psm);
    dim3 gf(HW/32, BB);
    k_fuse<<<gf, 512>>>(x, out);
}

// round 4
// speedup vs baseline: 2.3131x; 1.1451x over previous
#include <cuda_runtime.h>
#include <math.h>

#define BB 4
#define LL 5
#define TT 10
#define CC 64
#define HH 100
#define WW 352
#define NN (BB*LL)
#define HW (HH*WW)
#define H4 25
#define W4 88
#define P4 (H4*W4)

// scratch (no allocations allowed)
__device__ float g_tm4[NN*P4];
__device__ float g_has[NN];
__device__ unsigned char g_mask[NN*HW];

// 5x5 gaussian, sigma=1, scaled by 1/(2*pi*sigma)
__constant__ float c_G[25] = {
    0.0029150244947655228f, 0.013064233284684921f, 0.021539279301848634f, 0.013064233284684921f, 0.0029150244947655228f,
    0.013064233284684921f, 0.05854983152431917f, 0.09653235263005391f, 0.05854983152431917f, 0.013064233284684921f,
    0.021539279301848634f, 0.09653235263005391f, 0.15915494309189535f, 0.09653235263005391f, 0.021539279301848634f,
    0.013064233284684921f, 0.05854983152431917f, 0.09653235263005391f, 0.05854983152431917f, 0.013064233284684921f,
    0.0029150244947655228f, 0.013064233284684921f, 0.021539279301848634f, 0.013064233284684921f, 0.0029150244947655228f
};

// ---------------- K1: per-agent trajectory mask at H4 x W4 ----------------
// Conv weights staged through smem in 4 coalesced chunks (kills the 74K-wavefront
// L1tex serialization that cost 47us).
#define CONV_CHUNK 32                 // k's per chunk (128 total -> 4 chunks)
#define WROW 289                      // 32*9 padded to 289 (289 % 32 == 1: conflict-free)

__global__ void __launch_bounds__(512)
k_traj(const float* __restrict__ traj_all,
       const float* __restrict__ W1, const float* __restrict__ b1,
       const float* __restrict__ W2, const float* __restrict__ b2,
       const float* __restrict__ Wc1, const float* __restrict__ bc1,
       const float* __restrict__ Wc2, const float* __restrict__ bc2)
{
    extern __shared__ float s_wbuf[];   // 64 * WROW floats = 74 KB dynamic
    int n = blockIdx.x;
    int tid = threadIdx.x;
    __shared__ float s_tr[TT*3];
    __shared__ float s_h[64];
    __shared__ float s_f[128];
    __shared__ float s_pc[8][9][64];   // conv partials per k-group
    __shared__ float s_rel[9*64];
    __shared__ float s_a9[9];
    __shared__ int   s_xi[TT], s_yi[TT];
    __shared__ float s_m[P4];
    __shared__ float s_part[512];

    if (tid < TT*3) s_tr[tid] = traj_all[n*TT*3 + tid];
    __syncthreads();

    if (tid == 0) {
        int h = 0;
        for (int i = 0; i < TT*3; i++) if (s_tr[i] != 0.0f) h = 1;
        g_has[n] = (float)h;
    }
    if (tid < TT) {
        float px = s_tr[tid*3+0] / 0.4f;     // DISCRETE_RATIO
        float py = s_tr[tid*3+1] / 0.4f;
        int xi = (int)(px / 4.0f);           // truncation like .astype(int32)
        int yi = (int)(py / 4.0f);
        xi = min(max(xi, 0), W4-1);
        yi = min(max(yi, 0), H4-1);
        s_xi[tid] = xi; s_yi[tid] = yi;
    }
    // hbar = mean_t relu(traj @ W1 + b1)
    if (tid < 64) {
        float acc = 0.0f;
        for (int t = 0; t < TT; t++) {
            float z = b1[tid];
            z += s_tr[t*3+0]*W1[0*64+tid];
            z += s_tr[t*3+1]*W1[1*64+tid];
            z += s_tr[t*3+2]*W1[2*64+tid];
            acc += fmaxf(z, 0.0f);
        }
        s_h[tid] = acc * 0.1f;
    }
    __syncthreads();
    // f = hbar @ W2 + b2
    if (tid < 128) {
        float z = b2[tid];
        for (int c = 0; c < 64; c++) z += s_h[c]*W2[c*128+tid];
        s_f[tid] = z;
    }
    __syncthreads();

    // conv3x3 on spatially constant feature -> 9 border cases per channel.
    // Stage Wc1 chunk (64 o x 32 k x 9) coalesced into smem, then compute.
    {
        int o  = tid & 63;
        int kg = tid >> 6;              // 0..7, each handles 4 k's per chunk
        float a9[9];
        #pragma unroll
        for (int q = 0; q < 9; q++) a9[q] = 0.0f;

        for (int c = 0; c < 128/CONV_CHUNK; c++) {
            __syncthreads();
            // coalesced staged copy: per o, 288 consecutive floats
            for (int i = tid; i < 64*CONV_CHUNK*9; i += 512) {
                int oo = i / (CONV_CHUNK*9);
                int r  = i - oo*(CONV_CHUNK*9);
                s_wbuf[oo*WROW + r] = Wc1[(size_t)oo*1152 + c*(CONV_CHUNK*9) + r];
            }
            __syncthreads();
            #pragma unroll
            for (int kk = 0; kk < 4; kk++) {
                int kl = kg*4 + kk;
                float fk = s_f[c*CONV_CHUNK + kl];
                const float* w = s_wbuf + o*WROW + kl*9;
                float w00=w[0], w01=w[1], w02=w[2];
                float w10=w[3], w11=w[4], w12=w[5];
                float w20=w[6], w21=w[7], w22=w[8];
                float rF0=w00+w01+w02, rL0=w01+w02, rR0=w00+w01;
                float rF1=w10+w11+w12, rL1=w11+w12, rR1=w10+w11;
                float rF2=w20+w21+w22, rL2=w21+w22, rR2=w20+w21;
                a9[0] += fk*(rL1+rL2); a9[1] += fk*(rF1+rF2); a9[2] += fk*(rR1+rR2);
                a9[3] += fk*(rL0+rL1+rL2); a9[4] += fk*(rF0+rF1+rF2); a9[5] += fk*(rR0+rR1+rR2);
                a9[6] += fk*(rL0+rL1); a9[7] += fk*(rF0+rF1); a9[8] += fk*(rR0+rR1);
            }
        }
        #pragma unroll
        for (int q = 0; q < 9; q++) s_pc[kg][q][o] = a9[q];
    }
    __syncthreads();
    if (tid < 64) {
        #pragma unroll
        for (int q = 0; q < 9; q++) {
            float z = bc1[tid];
            #pragma unroll
            for (int g = 0; g < 8; g++) z += s_pc[g][q][tid];
            s_rel[q*64+tid] = fmaxf(z, 0.0f);
        }
    }
    __syncthreads();
    if (tid < 9) {
        float z = bc2[0];
        for (int c = 0; c < 64; c++) z += Wc2[c]*s_rel[tid*64+c];
        s_a9[tid] = 1.0f/(1.0f+expf(-z));
    }
    // gaussian splat
    float lsum = 0.0f;
    for (int p = tid; p < P4; p += 512) {
        int i = p / W4, j = p % W4;
        float m = 0.0f;
        #pragma unroll
        for (int t = 0; t < TT; t++) {
            int di = i - s_yi[t], dj = j - s_xi[t];
            if (di >= -3 && di <= 3 && dj >= -3 && dj <= 3)
                m += expf(-(float)(di*di+dj*dj)*0.125f);  // 2*sigma^2 = 8
        }
        s_m[p] = m; lsum += m;
    }
    s_part[tid] = lsum;
    __syncthreads();
    for (int off = 256; off > 0; off >>= 1) {
        if (tid < off) s_part[tid] += s_part[tid+off];
        __syncthreads();
    }
    float inv = 1.0f / fmaxf(s_part[0], 1e-12f);
    for (int p = tid; p < P4; p += 512) {
        int i = p / W4, j = p % W4;
        int r  = (i == 0) ? 0 : ((i == H4-1) ? 2 : 1);
        int cc = (j == 0) ? 0 : ((j == W4-1) ? 2 : 1);
        g_tm4[n*P4 + p] = s_m[p]*inv*s_a9[r*3+cc];
    }
}

// ---------------- K2: fused cmap + 5x5 smooth + threshold + ego force ----------------
// Tile 32x8, halo 2 -> 36x12 cmap values computed in smem (zero outside = conv zero-pad).
__global__ void __launch_bounds__(256)
k_cmask(const float* __restrict__ psm)
{
    __shared__ float s_c[12][36];
    int n  = blockIdx.z;
    int bx = blockIdx.x * 32;
    int by = blockIdx.y * 8;
    int tid = threadIdx.x;

    const float* tmn = g_tm4 + n*P4;
    float has = g_has[n];

    for (int i = tid; i < 12*36; i += 256) {
        int ly = i / 36, lx = i - ly*36;
        int gx = bx + lx - 2, gy = by + ly - 2;
        float val = 0.0f;
        if (gx >= 0 && gx < WW && gy >= 0 && gy < HH) {
            float uy = fminf(fmaxf((gy+0.5f)*0.25f - 0.5f, 0.0f), (float)(H4-1));
            float ux = fminf(fmaxf((gx+0.5f)*0.25f - 0.5f, 0.0f), (float)(W4-1));
            int y0 = (int)uy, x0 = (int)ux;
            float fy = uy - y0, fx = ux - x0;
            int y1 = min(y0+1, H4-1), x1 = min(x0+1, W4-1);
            float v00 = tmn[y0*W4+x0], v01 = tmn[y0*W4+x1];
            float v10 = tmn[y1*W4+x0], v11 = tmn[y1*W4+x1];
            float tm = v00*(1.0f-fy)*(1.0f-fx) + v01*(1.0f-fy)*fx
                     + v10*fy*(1.0f-fx)        + v11*fy*fx;
            float fac = 1.0f + has*tm;
            int p = gy*WW + gx;
            float a0 = psm[(size_t)(n*2+0)*HW + p]*fac;
            float a1 = psm[(size_t)(n*2+1)*HW + p]*fac;
            float c0 = 1.0f/(1.0f+expf(-a0));
            float c1 = 1.0f/(1.0f+expf(-a1));
            val = fmaxf(c0, c1);
        }
        s_c[ly][lx] = val;
    }
    __syncthreads();

    int lx = tid & 31, ly = tid >> 5;
    int gx = bx + lx, gy = by + ly;
    if (gy < HH) {
        float acc = 0.0f;
        #pragma unroll
        for (int dy = 0; dy < 5; dy++) {
            #pragma unroll
            for (int dx = 0; dx < 5; dx++)
                acc += c_G[dy*5+dx] * s_c[ly+dy][lx+dx];
        }
        int l = n % LL;
        g_mask[(size_t)n*HW + gy*WW + gx] = (l == 0) ? 1 : ((acc > 0.01f) ? 1 : 0);
    }
}

// ---------------- K3: masked ego-row attention fusion (register-resident) ----------------
// Block = 32 pixels x 16 channel-groups (4 ch each). x read exactly once, all fp32.
__global__ void __launch_bounds__(512, 3)
k_fuse(const float* __restrict__ x, float* __restrict__ out)
{
    __shared__ float s_d[16][5][32];
    __shared__ float s_w[5][32];

    int px = threadIdx.x & 31;
    int cg = threadIdx.x >> 5;        // 0..15
    int p  = blockIdx.x * 32 + px;    // HW = 35200 = 1100 * 32
    int b  = blockIdx.y;

    const float* xb = x + (size_t)b*LL*CC*HW + p;

    float mk[LL];
    #pragma unroll
    for (int m = 0; m < LL; m++)
        mk[m] = (float)g_mask[(size_t)(b*LL+m)*HW + p];

    float v[LL][4];
    #pragma unroll
    for (int m = 0; m < LL; m++) {
        #pragma unroll
        for (int i = 0; i < 4; i++)
            v[m][i] = xb[(size_t)(m*CC + cg*4 + i)*HW] * mk[m];
    }

    float d[LL];
    #pragma unroll
    for (int m = 0; m < LL; m++) d[m] = 0.0f;
    #pragma unroll
    for (int i = 0; i < 4; i++) {
        #pragma unroll
        for (int m = 0; m < LL; m++) d[m] += v[0][i]*v[m][i];
    }
    #pragma unroll
    for (int m = 0; m < LL; m++) s_d[cg][m][px] = d[m];
    __syncthreads();

    if (cg == 0) {   // warp 0 finishes dots + softmax
        float s[LL];
        #pragma unroll
        for (int m = 0; m < LL; m++) {
            float acc = 0.0f;
            #pragma unroll
            for (int g = 0; g < 16; g++) acc += s_d[g][m][px];
            s[m] = acc * 0.125f;   // 1/sqrt(64)
        }
        float mx = fmaxf(fmaxf(fmaxf(s[0], s[1]), fmaxf(s[2], s[3])), s[4]);
        float e[LL], sum = 0.0f;
        #pragma unroll
        for (int m = 0; m < LL; m++) { e[m] = expf(s[m]-mx); sum += e[m]; }
        float isum = 1.0f/sum;
        #pragma unroll
        for (int m = 0; m < LL; m++) s_w[m][px] = e[m]*isum;
    }
    __syncthreads();

    float w[LL];
    #pragma unroll
    for (int m = 0; m < LL; m++) w[m] = s_w[m][px];

    float* ob = out + (size_t)b*CC*HW + p;
    #pragma unroll
    for (int i = 0; i < 4; i++) {
        float acc = w[0]*v[0][i] + w[1]*v[1][i] + w[2]*v[2][i]
                  + w[3]*v[3][i] + w[4]*v[4][i];
        ob[(size_t)(cg*4+i)*HW] = acc;
    }
}

extern "C" void kernel_launch(void* const* d_in, const int* in_sizes, int n_in,
                              void* d_out, int out_size)
{
    const float* x    = (const float*)d_in[0];
    const float* psm  = (const float*)d_in[1];
    // d_in[2] record_len, d_in[3] pairwise_t_matrix: unused by reference
    const float* traj = (const float*)d_in[4];
    const float* W1   = (const float*)d_in[5];
    const float* b1   = (const float*)d_in[6];
    const float* W2   = (const float*)d_in[7];
    const float* b2   = (const float*)d_in[8];
    const float* Wc1  = (const float*)d_in[9];
    const float* bc1  = (const float*)d_in[10];
    const float* Wc2  = (const float*)d_in[11];
    const float* bc2  = (const float*)d_in[12];
    float* out = (float*)d_out;

    const int traj_dyn = 64*WROW*(int)sizeof(float);   // ~74 KB
    cudaFuncSetAttribute((const void*)k_traj,
                         cudaFuncAttributeMaxDynamicSharedMemorySize, traj_dyn);

    k_traj<<<NN, 512, traj_dyn>>>(traj, W1, b1, W2, b2, Wc1, bc1, Wc2, bc2);
    dim3 gm(WW/32, (HH+7)/8, NN);
    k_cmask<<<gm, 256>>>(psm);
    dim3 gf(HW/32, BB);
    k_fuse<<<gf, 512>>>(x, out);
}

// round 5
// speedup vs baseline: 2.8958x; 1.2519x over previous
#include <cuda_runtime.h>
#include <math.h>

#define BB 4
#define LL 5
#define TT 10
#define CC 64
#define HH 100
#define WW 352
#define NN (BB*LL)
#define HW (HH*WW)
#define H4 25
#define W4 88
#define P4 (H4*W4)

// scratch (no allocations allowed)
__device__ float g_tm4[NN*P4];
__device__ float g_has[NN];
__device__ unsigned char g_mask[NN*HW];
__device__ float g_f[NN*128];
__device__ float g_R[9*128*64];       // conv weights pre-reduced to 9 border cases
__device__ int   g_xi[NN*TT], g_yi[NN*TT];

// 5x5 gaussian, sigma=1, scaled by 1/(2*pi*sigma)
__constant__ float c_G[25] = {
    0.0029150244947655228f, 0.013064233284684921f, 0.021539279301848634f, 0.013064233284684921f, 0.0029150244947655228f,
    0.013064233284684921f, 0.05854983152431917f, 0.09653235263005391f, 0.05854983152431917f, 0.013064233284684921f,
    0.021539279301848634f, 0.09653235263005391f, 0.15915494309189535f, 0.09653235263005391f, 0.021539279301848634f,
    0.013064233284684921f, 0.05854983152431917f, 0.09653235263005391f, 0.05854983152431917f, 0.013064233284684921f,
    0.0029150244947655228f, 0.013064233284684921f, 0.021539279301848634f, 0.013064233284684921f, 0.0029150244947655228f
};

// 7x7 splat table: exp(-(di^2+dj^2)/8), di,dj in [-3,3]
__constant__ float c_g7[49] = {
    0.10539922456186433f, 0.19689917292530676f, 0.2865047968601901f, 0.32465246735834974f, 0.2865047968601901f, 0.19689917292530676f, 0.10539922456186433f,
    0.19689917292530676f, 0.36787944117144233f, 0.5352614285189903f, 0.6065306597126334f, 0.5352614285189903f, 0.36787944117144233f, 0.19689917292530676f,
    0.2865047968601901f, 0.5352614285189903f, 0.7788007830714049f, 0.8824969025845955f, 0.7788007830714049f, 0.5352614285189903f, 0.2865047968601901f,
    0.32465246735834974f, 0.6065306597126334f, 0.8824969025845955f, 1.0f, 0.8824969025845955f, 0.6065306597126334f, 0.32465246735834974f,
    0.2865047968601901f, 0.5352614285189903f, 0.7788007830714049f, 0.8824969025845955f, 0.7788007830714049f, 0.5352614285189903f, 0.2865047968601901f,
    0.19689917292530676f, 0.36787944117144233f, 0.5352614285189903f, 0.6065306597126334f, 0.5352614285189903f, 0.36787944117144233f, 0.19689917292530676f,
    0.10539922456186433f, 0.19689917292530676f, 0.2865047968601901f, 0.32465246735834974f, 0.2865047968601901f, 0.19689917292530676f, 0.10539922456186433f
};

// ---------------- K1: prep. Blocks 0..127: reduce Wc1 -> R. Blocks 128..147: per-agent MLP ----------------
__global__ void __launch_bounds__(128)
k_prep(const float* __restrict__ traj_all,
       const float* __restrict__ W1, const float* __restrict__ b1,
       const float* __restrict__ W2, const float* __restrict__ b2,
       const float* __restrict__ Wc1)
{
    int bid = blockIdx.x;
    int tid = threadIdx.x;

    if (bid < 128) {
        // R[q][k][o]: per (k=bid, o=tid<64), fold 3x3 into 9 border-case sums
        if (tid < 64) {
            int k = bid, o = tid;
            const float* w = Wc1 + (size_t)o*1152 + k*9;
            float w00=w[0], w01=w[1], w02=w[2];
            float w10=w[3], w11=w[4], w12=w[5];
            float w20=w[6], w21=w[7], w22=w[8];
            float rF0=w00+w01+w02, rL0=w01+w02, rR0=w00+w01;
            float rF1=w10+w11+w12, rL1=w11+w12, rR1=w10+w11;
            float rF2=w20+w21+w22, rL2=w21+w22, rR2=w20+w21;
            float q0=rL1+rL2, q1=rF1+rF2, q2=rR1+rR2;
            float q3=rL0+rL1+rL2, q4=rF0+rF1+rF2, q5=rR0+rR1+rR2;
            float q6=rL0+rL1, q7=rF0+rF1, q8=rR0+rR1;
            g_R[(0*128+k)*64+o]=q0; g_R[(1*128+k)*64+o]=q1; g_R[(2*128+k)*64+o]=q2;
            g_R[(3*128+k)*64+o]=q3; g_R[(4*128+k)*64+o]=q4; g_R[(5*128+k)*64+o]=q5;
            g_R[(6*128+k)*64+o]=q6; g_R[(7*128+k)*64+o]=q7; g_R[(8*128+k)*64+o]=q8;
        }
        return;
    }

    int n = bid - 128;
    __shared__ float s_tr[TT*3];
    __shared__ float s_h[64];
    if (tid < TT*3) s_tr[tid] = traj_all[n*TT*3 + tid];
    __syncthreads();

    if (tid == 0) {
        int h = 0;
        for (int i = 0; i < TT*3; i++) if (s_tr[i] != 0.0f) h = 1;
        g_has[n] = (float)h;
    }
    if (tid < TT) {
        float px = s_tr[tid*3+0] / 0.4f;     // DISCRETE_RATIO
        float py = s_tr[tid*3+1] / 0.4f;
        int xi = (int)(px / 4.0f);           // truncation like .astype(int32)
        int yi = (int)(py / 4.0f);
        g_xi[n*TT+tid] = min(max(xi, 0), W4-1);
        g_yi[n*TT+tid] = min(max(yi, 0), H4-1);
    }
    // hbar = mean_t relu(traj @ W1 + b1)
    if (tid < 64) {
        float acc = 0.0f;
        #pragma unroll
        for (int t = 0; t < TT; t++) {
            float z = b1[tid];
            z += s_tr[t*3+0]*W1[0*64+tid];
            z += s_tr[t*3+1]*W1[1*64+tid];
            z += s_tr[t*3+2]*W1[2*64+tid];
            acc += fmaxf(z, 0.0f);
        }
        s_h[tid] = acc * 0.1f;
    }
    __syncthreads();
    // f = hbar @ W2 + b2
    {
        float z = b2[tid];
        #pragma unroll 8
        for (int c = 0; c < 64; c++) z += s_h[c]*W2[c*128+tid];
        g_f[n*128+tid] = z;
    }
}

// ---------------- K2: per-agent attention(9 cases) + table splat + normalize ----------------
__global__ void __launch_bounds__(576)
k_traj2(const float* __restrict__ bc1, const float* __restrict__ Wc2,
        const float* __restrict__ bc2)
{
    int n = blockIdx.x;
    int tid = threadIdx.x;
    __shared__ float s_f[128];
    __shared__ float s_a9[9];
    __shared__ float s_red[9][2];
    __shared__ int   s_xi[TT], s_yi[TT];
    __shared__ float s_g7[49];
    __shared__ float s_m[P4];
    __shared__ float s_wsum[18];

    if (tid < 128) s_f[tid] = g_f[n*128+tid];
    if (tid < TT) { s_xi[tid] = g_xi[n*TT+tid]; s_yi[tid] = g_yi[n*TT+tid]; }
    if (tid >= 128 && tid < 128+49) s_g7[tid-128] = c_g7[tid-128];
    __syncthreads();

    // z[q][o] = bc1[o] + sum_k f[k]*R[q][k][o]; 576 = 9 q-groups x 64 o
    {
        int q = tid / 64, o = tid & 63;
        float acc = bc1[o];
        const float* Rp = g_R + (size_t)q*128*64 + o;
        #pragma unroll 8
        for (int k = 0; k < 128; k++) acc += s_f[k] * Rp[(size_t)k*64];
        float t = Wc2[o] * fmaxf(acc, 0.0f);
        // reduce over 64 o (2 warps per q-group)
        #pragma unroll
        for (int off = 16; off > 0; off >>= 1)
            t += __shfl_down_sync(0xFFFFFFFFu, t, off);
        if ((tid & 31) == 0) s_red[q][(tid >> 5) & 1] = t;
    }
    __syncthreads();
    if (tid < 9) {
        float z = bc2[0] + s_red[tid][0] + s_red[tid][1];
        s_a9[tid] = 1.0f/(1.0f+expf(-z));
    }
    __syncthreads();

    // gaussian splat from 7x7 table
    float lsum = 0.0f;
    for (int p = tid; p < P4; p += 576) {
        int i = p / W4, j = p - (p / W4)*W4;
        float m = 0.0f;
        #pragma unroll
        for (int t = 0; t < TT; t++) {
            int di = i - s_yi[t] + 3, dj = j - s_xi[t] + 3;
            if ((unsigned)di < 7u && (unsigned)dj < 7u) m += s_g7[di*7+dj];
        }
        s_m[p] = m; lsum += m;
    }
    #pragma unroll
    for (int off = 16; off > 0; off >>= 1)
        lsum += __shfl_down_sync(0xFFFFFFFFu, lsum, off);
    if ((tid & 31) == 0) s_wsum[tid >> 5] = lsum;
    __syncthreads();
    if (tid == 0) {
        float t = 0.0f;
        #pragma unroll
        for (int w = 0; w < 18; w++) t += s_wsum[w];
        s_wsum[0] = 1.0f / fmaxf(t, 1e-12f);
    }
    __syncthreads();
    float inv = s_wsum[0];
    for (int p = tid; p < P4; p += 576) {
        int i = p / W4, j = p - (p / W4)*W4;
        int r  = (i == 0) ? 0 : ((i == H4-1) ? 2 : 1);
        int cc = (j == 0) ? 0 : ((j == W4-1) ? 2 : 1);
        g_tm4[n*P4 + p] = s_m[p]*inv*s_a9[r*3+cc];
    }
}

// ---------------- K3: fused cmap + 5x5 smooth + threshold + ego force ----------------
// Tile 32x8, halo 2 -> 36x12 cmap values computed in smem (zero outside = conv zero-pad).
__global__ void __launch_bounds__(256)
k_cmask(const float* __restrict__ psm)
{
    __shared__ float s_c[12][36];
    int n  = blockIdx.z;
    int bx = blockIdx.x * 32;
    int by = blockIdx.y * 8;
    int tid = threadIdx.x;

    const float* tmn = g_tm4 + n*P4;
    float has = g_has[n];

    for (int i = tid; i < 12*36; i += 256) {
        int ly = i / 36, lx = i - ly*36;
        int gx = bx + lx - 2, gy = by + ly - 2;
        float val = 0.0f;
        if (gx >= 0 && gx < WW && gy >= 0 && gy < HH) {
            float uy = fminf(fmaxf((gy+0.5f)*0.25f - 0.5f, 0.0f), (float)(H4-1));
            float ux = fminf(fmaxf((gx+0.5f)*0.25f - 0.5f, 0.0f), (float)(W4-1));
            int y0 = (int)uy, x0 = (int)ux;
            float fy = uy - y0, fx = ux - x0;
            int y1 = min(y0+1, H4-1), x1 = min(x0+1, W4-1);
            float v00 = tmn[y0*W4+x0], v01 = tmn[y0*W4+x1];
            float v10 = tmn[y1*W4+x0], v11 = tmn[y1*W4+x1];
            float tm = v00*(1.0f-fy)*(1.0f-fx) + v01*(1.0f-fy)*fx
                     + v10*fy*(1.0f-fx)        + v11*fy*fx;
            float fac = 1.0f + has*tm;
            int p = gy*WW + gx;
            float a0 = psm[(size_t)(n*2+0)*HW + p]*fac;
            float a1 = psm[(size_t)(n*2+1)*HW + p]*fac;
            float c0 = 1.0f/(1.0f+expf(-a0));
            float c1 = 1.0f/(1.0f+expf(-a1));
            val = fmaxf(c0, c1);
        }
        s_c[ly][lx] = val;
    }
    __syncthreads();

    int lx = tid & 31, ly = tid >> 5;
    int gx = bx + lx, gy = by + ly;
    if (gy < HH) {
        float acc = 0.0f;
        #pragma unroll
        for (int dy = 0; dy < 5; dy++) {
            #pragma unroll
            for (int dx = 0; dx < 5; dx++)
                acc += c_G[dy*5+dx] * s_c[ly+dy][lx+dx];
        }
        int l = n % LL;
        g_mask[(size_t)n*HW + gy*WW + gx] = (l == 0) ? 1 : ((acc > 0.01f) ? 1 : 0);
    }
}

// ---------------- K4: masked ego-row attention fusion (register-resident) ----------------
// Block = 32 pixels x 16 channel-groups (4 ch each). x read exactly once, all fp32.
__global__ void __launch_bounds__(512, 3)
k_fuse(const float* __restrict__ x, float* __restrict__ out)
{
    __shared__ float s_d[16][5][32];
    __shared__ float s_w[5][32];

    int px = threadIdx.x & 31;
    int cg = threadIdx.x >> 5;        // 0..15
    int p  = blockIdx.x * 32 + px;    // HW = 35200 = 1100 * 32
    int b  = blockIdx.y;

    const float* xb = x + (size_t)b*LL*CC*HW + p;

    float mk[LL];
    #pragma unroll
    for (int m = 0; m < LL; m++)
        mk[m] = (float)g_mask[(size_t)(b*LL+m)*HW + p];

    float v[LL][4];
    #pragma unroll
    for (int m = 0; m < LL; m++) {
        #pragma unroll
        for (int i = 0; i < 4; i++)
            v[m][i] = xb[(size_t)(m*CC + cg*4 + i)*HW] * mk[m];
    }

    float d[LL];
    #pragma unroll
    for (int m = 0; m < LL; m++) d[m] = 0.0f;
    #pragma unroll
    for (int i = 0; i < 4; i++) {
        #pragma unroll
        for (int m = 0; m < LL; m++) d[m] += v[0][i]*v[m][i];
    }
    #pragma unroll
    for (int m = 0; m < LL; m++) s_d[cg][m][px] = d[m];
    __syncthreads();

    if (cg == 0) {   // warp 0 finishes dots + softmax
        float s[LL];
        #pragma unroll
        for (int m = 0; m < LL; m++) {
            float acc = 0.0f;
            #pragma unroll
            for (int g = 0; g < 16; g++) acc += s_d[g][m][px];
            s[m] = acc * 0.125f;   // 1/sqrt(64)
        }
        float mx = fmaxf(fmaxf(fmaxf(s[0], s[1]), fmaxf(s[2], s[3])), s[4]);
        float e[LL], sum = 0.0f;
        #pragma unroll
        for (int m = 0; m < LL; m++) { e[m] = expf(s[m]-mx); sum += e[m]; }
        float isum = 1.0f/sum;
        #pragma unroll
        for (int m = 0; m < LL; m++) s_w[m][px] = e[m]*isum;
    }
    __syncthreads();

    float w[LL];
    #pragma unroll
    for (int m = 0; m < LL; m++) w[m] = s_w[m][px];

    float* ob = out + (size_t)b*CC*HW + p;
    #pragma unroll
    for (int i = 0; i < 4; i++) {
        float acc = w[0]*v[0][i] + w[1]*v[1][i] + w[2]*v[2][i]
                  + w[3]*v[3][i] + w[4]*v[4][i];
        ob[(size_t)(cg*4+i)*HW] = acc;
    }
}

extern "C" void kernel_launch(void* const* d_in, const int* in_sizes, int n_in,
                              void* d_out, int out_size)
{
    const float* x    = (const float*)d_in[0];
    const float* psm  = (const float*)d_in[1];
    // d_in[2] record_len, d_in[3] pairwise_t_matrix: unused by reference
    const float* traj = (const float*)d_in[4];
    const float* W1   = (const float*)d_in[5];
    const float* b1   = (const float*)d_in[6];
    const float* W2   = (const float*)d_in[7];
    const float* b2   = (const float*)d_in[8];
    const float* Wc1  = (const float*)d_in[9];
    const float* bc1  = (const float*)d_in[10];
    const float* Wc2  = (const float*)d_in[11];
    const float* bc2  = (const float*)d_in[12];
    float* out = (float*)d_out;

    k_prep<<<148, 128>>>(traj, W1, b1, W2, b2, Wc1);
    k_traj2<<<NN, 576>>>(bc1, Wc2, bc2);
    dim3 gm(WW/32, (HH+7)/8, NN);
    k_cmask<<<gm, 256>>>(psm);
    dim3 gf(HW/32, BB);
    k_fuse<<<gf, 512>>>(x, out);
}

// round 7
// speedup vs baseline: 3.0889x; 1.0667x over previous
#include <cuda_runtime.h>
#include <math.h>

#define BB 4
#define LL 5
#define TT 10
#define CC 64
#define HH 100
#define WW 352
#define NN (BB*LL)
#define HW (HH*WW)
#define H4 25
#define W4 88
#define P4 (H4*W4)

// scratch (no allocations allowed)
__device__ float g_tm4[NN*P4];
__device__ float g_has[NN];
__device__ unsigned char g_mask[NN*HW];
__device__ float g_f[NN*128];
__device__ float g_R[9*128*64];       // conv weights pre-reduced to 9 border cases
__device__ int   g_xi[NN*TT], g_yi[NN*TT];

// fast sigmoid via tanh.approx (mask path only -- feeds a 0.01 threshold, never the output values)
__device__ __forceinline__ float fast_sigmoid(float xv) {
    float t;
    asm("tanh.approx.f32 %0, %1;" : "=f"(t) : "f"(xv*0.5f));
    return fmaf(t, 0.5f, 0.5f);
}

// 5x5 gaussian, sigma=1, scaled by 1/(2*pi*sigma)
__constant__ float c_G[25] = {
    0.0029150244947655228f, 0.013064233284684921f, 0.021539279301848634f, 0.013064233284684921f, 0.0029150244947655228f,
    0.013064233284684921f, 0.05854983152431917f, 0.09653235263005391f, 0.05854983152431917f, 0.013064233284684921f,
    0.021539279301848634f, 0.09653235263005391f, 0.15915494309189535f, 0.09653235263005391f, 0.021539279301848634f,
    0.013064233284684921f, 0.05854983152431917f, 0.09653235263005391f, 0.05854983152431917f, 0.013064233284684921f,
    0.0029150244947655228f, 0.013064233284684921f, 0.021539279301848634f, 0.013064233284684921f, 0.0029150244947655228f
};

// 7x7 splat table: exp(-(di^2+dj^2)/8), di,dj in [-3,3]
__constant__ float c_g7[49] = {
    0.10539922456186433f, 0.19689917292530676f, 0.2865047968601901f, 0.32465246735834974f, 0.2865047968601901f, 0.19689917292530676f, 0.10539922456186433f,
    0.19689917292530676f, 0.36787944117144233f, 0.5352614285189903f, 0.6065306597126334f, 0.5352614285189903f, 0.36787944117144233f, 0.19689917292530676f,
    0.2865047968601901f, 0.5352614285189903f, 0.7788007830714049f, 0.8824969025845955f, 0.7788007830714049f, 0.5352614285189903f, 0.2865047968601901f,
    0.32465246735834974f, 0.6065306597126334f, 0.8824969025845955f, 1.0f, 0.8824969025845955f, 0.6065306597126334f, 0.32465246735834974f,
    0.2865047968601901f, 0.5352614285189903f, 0.7788007830714049f, 0.8824969025845955f, 0.7788007830714049f, 0.5352614285189903f, 0.2865047968601901f,
    0.19689917292530676f, 0.36787944117144233f, 0.5352614285189903f, 0.6065306597126334f, 0.5352614285189903f, 0.36787944117144233f, 0.19689917292530676f,
    0.10539922456186433f, 0.19689917292530676f, 0.2865047968601901f, 0.32465246735834974f, 0.2865047968601901f, 0.19689917292530676f, 0.10539922456186433f
};

// ---------------- K1: prep. Blocks 0..127: reduce Wc1 -> R. Blocks 128..147: per-agent MLP ----------------
__global__ void __launch_bounds__(128)
k_prep(const float* __restrict__ traj_all,
       const float* __restrict__ W1, const float* __restrict__ b1,
       const float* __restrict__ W2, const float* __restrict__ b2,
       const float* __restrict__ Wc1)
{
    int bid = blockIdx.x;
    int tid = threadIdx.x;

    if (bid < 128) {
        if (tid < 64) {
            int k = bid, o = tid;
            const float* w = Wc1 + (size_t)o*1152 + k*9;
            float w00=w[0], w01=w[1], w02=w[2];
            float w10=w[3], w11=w[4], w12=w[5];
            float w20=w[6], w21=w[7], w22=w[8];
            float rF0=w00+w01+w02, rL0=w01+w02, rR0=w00+w01;
            float rF1=w10+w11+w12, rL1=w11+w12, rR1=w10+w11;
            float rF2=w20+w21+w22, rL2=w21+w22, rR2=w20+w21;
            g_R[(0*128+k)*64+o]=rL1+rL2; g_R[(1*128+k)*64+o]=rF1+rF2; g_R[(2*128+k)*64+o]=rR1+rR2;
            g_R[(3*128+k)*64+o]=rL0+rL1+rL2; g_R[(4*128+k)*64+o]=rF0+rF1+rF2; g_R[(5*128+k)*64+o]=rR0+rR1+rR2;
            g_R[(6*128+k)*64+o]=rL0+rL1; g_R[(7*128+k)*64+o]=rF0+rF1; g_R[(8*128+k)*64+o]=rR0+rR1;
        }
        return;
    }

    int n = bid - 128;
    __shared__ float s_tr[TT*3];
    __shared__ float s_h[64];
    if (tid < TT*3) s_tr[tid] = traj_all[n*TT*3 + tid];
    __syncthreads();

    if (tid == 0) {
        int h = 0;
        for (int i = 0; i < TT*3; i++) if (s_tr[i] != 0.0f) h = 1;
        g_has[n] = (float)h;
    }
    if (tid < TT) {
        float px = s_tr[tid*3+0] / 0.4f;     // DISCRETE_RATIO
        float py = s_tr[tid*3+1] / 0.4f;
        int xi = (int)(px / 4.0f);           // truncation like .astype(int32)
        int yi = (int)(py / 4.0f);
        g_xi[n*TT+tid] = min(max(xi, 0), W4-1);
        g_yi[n*TT+tid] = min(max(yi, 0), H4-1);
    }
    if (tid < 64) {
        float acc = 0.0f;
        #pragma unroll
        for (int t = 0; t < TT; t++) {
            float z = b1[tid];
            z += s_tr[t*3+0]*W1[0*64+tid];
            z += s_tr[t*3+1]*W1[1*64+tid];
            z += s_tr[t*3+2]*W1[2*64+tid];
            acc += fmaxf(z, 0.0f);
        }
        s_h[tid] = acc * 0.1f;
    }
    __syncthreads();
    {
        float z = b2[tid];
        #pragma unroll 8
        for (int c = 0; c < 64; c++) z += s_h[c]*W2[c*128+tid];
        g_f[n*128+tid] = z;
    }
}

// ---------------- K2: per-agent attention(9 cases) + table splat + normalize ----------------
__global__ void __launch_bounds__(576)
k_traj2(const float* __restrict__ bc1, const float* __restrict__ Wc2,
        const float* __restrict__ bc2)
{
    int n = blockIdx.x;
    int tid = threadIdx.x;
    __shared__ float s_f[128];
    __shared__ float s_a9[9];
    __shared__ float s_red[9][2];
    __shared__ int   s_xi[TT], s_yi[TT];
    __shared__ float s_g7[49];
    __shared__ float s_m[P4];
    __shared__ float s_wsum[18];

    if (tid < 128) s_f[tid] = g_f[n*128+tid];
    if (tid < TT) { s_xi[tid] = g_xi[n*TT+tid]; s_yi[tid] = g_yi[n*TT+tid]; }
    if (tid >= 128 && tid < 128+49) s_g7[tid-128] = c_g7[tid-128];
    __syncthreads();

    {
        int q = tid / 64, o = tid & 63;
        float acc = bc1[o];
        const float* Rp = g_R + (size_t)q*128*64 + o;
        #pragma unroll 8
        for (int k = 0; k < 128; k++) acc += s_f[k] * Rp[(size_t)k*64];
        float t = Wc2[o] * fmaxf(acc, 0.0f);
        #pragma unroll
        for (int off = 16; off > 0; off >>= 1)
            t += __shfl_down_sync(0xFFFFFFFFu, t, off);
        if ((tid & 31) == 0) s_red[q][(tid >> 5) & 1] = t;
    }
    __syncthreads();
    if (tid < 9) {
        float z = bc2[0] + s_red[tid][0] + s_red[tid][1];
        s_a9[tid] = fast_sigmoid(z);
    }
    __syncthreads();

    float lsum = 0.0f;
    for (int p = tid; p < P4; p += 576) {
        int i = p / W4, j = p - (p / W4)*W4;
        float m = 0.0f;
        #pragma unroll
        for (int t = 0; t < TT; t++) {
            int di = i - s_yi[t] + 3, dj = j - s_xi[t] + 3;
            if ((unsigned)di < 7u && (unsigned)dj < 7u) m += s_g7[di*7+dj];
        }
        s_m[p] = m; lsum += m;
    }
    #pragma unroll
    for (int off = 16; off > 0; off >>= 1)
        lsum += __shfl_down_sync(0xFFFFFFFFu, lsum, off);
    if ((tid & 31) == 0) s_wsum[tid >> 5] = lsum;
    __syncthreads();
    if (tid == 0) {
        float t = 0.0f;
        #pragma unroll
        for (int w = 0; w < 18; w++) t += s_wsum[w];
        s_wsum[0] = 1.0f / fmaxf(t, 1e-12f);
    }
    __syncthreads();
    float inv = s_wsum[0];
    for (int p = tid; p < P4; p += 576) {
        int i = p / W4, j = p - (p / W4)*W4;
        int r  = (i == 0) ? 0 : ((i == H4-1) ? 2 : 1);
        int cc = (j == 0) ? 0 : ((j == W4-1) ? 2 : 1);
        g_tm4[n*P4 + p] = s_m[p]*inv*s_a9[r*3+cc];
    }
}

// ---------------- K3: fused cmap + 5x5 smooth + threshold + ego force ----------------
// Tile 32x16, halo 2 -> 36x20 cmap values in smem (zero outside = conv zero-pad).
__global__ void __launch_bounds__(256)
k_cmask(const float* __restrict__ psm)
{
    __shared__ float s_c[20][36];
    int n  = blockIdx.z;
    int bx = blockIdx.x * 32;
    int by = blockIdx.y * 16;
    int tid = threadIdx.x;

    const float* tmn = g_tm4 + n*P4;
    float has = g_has[n];

    for (int i = tid; i < 20*36; i += 256) {
        int ly = i / 36, lx = i - ly*36;
        int gx = bx + lx - 2, gy = by + ly - 2;
        float val = 0.0f;
        if (gx >= 0 && gx < WW && gy >= 0 && gy < HH) {
            float uy = fminf(fmaxf((gy+0.5f)*0.25f - 0.5f, 0.0f), (float)(H4-1));
            float ux = fminf(fmaxf((gx+0.5f)*0.25f - 0.5f, 0.0f), (float)(W4-1));
            int y0 = (int)uy, x0 = (int)ux;
            float fy = uy - y0, fx = ux - x0;
            int y1 = min(y0+1, H4-1), x1 = min(x0+1, W4-1);
            float v00 = tmn[y0*W4+x0], v01 = tmn[y0*W4+x1];
            float v10 = tmn[y1*W4+x0], v11 = tmn[y1*W4+x1];
            float tm = v00*(1.0f-fy)*(1.0f-fx) + v01*(1.0f-fy)*fx
                     + v10*fy*(1.0f-fx)        + v11*fy*fx;
            float fac = 1.0f + has*tm;
            int p = gy*WW + gx;
            float c0 = fast_sigmoid(psm[(size_t)(n*2+0)*HW + p]*fac);
            float c1 = fast_sigmoid(psm[(size_t)(n*2+1)*HW + p]*fac);
            val = fmaxf(c0, c1);
        }
        s_c[ly][lx] = val;
    }
    __syncthreads();

    int lx = tid & 31;
    int l  = n % LL;
    unsigned char* mb = g_mask + (size_t)n*HW;
    #pragma unroll
    for (int r = 0; r < 2; r++) {
        int ly = (tid >> 5) + r*8;
        int gx = bx + lx, gy = by + ly;
        if (gy < HH) {
            float acc = 0.0f;
            #pragma unroll
            for (int dy = 0; dy < 5; dy++) {
                #pragma unroll
                for (int dx = 0; dx < 5; dx++)
                    acc += c_G[dy*5+dx] * s_c[ly+dy][lx+dx];
            }
            mb[gy*WW + gx] = (l == 0) ? 1 : ((acc > 0.01f) ? 1 : 0);
        }
    }
}

// ---------------- K4: masked ego-row attention fusion ----------------
// 256 thr = 32 px x 8 channel-groups; single barrier; redundant per-thread softmax.
__global__ void __launch_bounds__(256)
k_fuse(const float* __restrict__ x, float* __restrict__ out)
{
    __shared__ float s_d[8][5][32];

    int px = threadIdx.x & 31;
    int cg = threadIdx.x >> 5;        // 0..7
    int p  = blockIdx.x * 32 + px;    // HW = 35200 = 1100 * 32
    int b  = blockIdx.y;

    const float* xb = x + (size_t)b*LL*CC*HW + p;

    float mk[LL];
    #pragma unroll
    for (int m = 0; m < LL; m++)
        mk[m] = (float)g_mask[(size_t)(b*LL+m)*HW + p];

    float v[LL][8];
    #pragma unroll
    for (int m = 0; m < LL; m++) {
        #pragma unroll
        for (int i = 0; i < 8; i++)
            v[m][i] = xb[(size_t)(m*CC + cg*8 + i)*HW] * mk[m];
    }

    float d[LL];
    #pragma unroll
    for (int m = 0; m < LL; m++) d[m] = 0.0f;
    #pragma unroll
    for (int i = 0; i < 8; i++) {
        #pragma unroll
        for (int m = 0; m < LL; m++) d[m] += v[0][i]*v[m][i];
    }
    #pragma unroll
    for (int m = 0; m < LL; m++) s_d[cg][m][px] = d[m];
    __syncthreads();

    // every thread reduces the 8 partials itself and computes softmax (no 2nd barrier)
    float e[LL], sum = 0.0f;
    #pragma unroll
    for (int m = 0; m < LL; m++) {
        float acc = 0.0f;
        #pragma unroll
        for (int g = 0; g < 8; g++) acc += s_d[g][m][px];
        e[m] = __expf(acc * 0.125f);   // exponents bounded ~20: no max-subtract needed
        sum += e[m];
    }
    float isum = 1.0f/sum;

    float* ob = out + (size_t)b*CC*HW + p;
    #pragma unroll
    for (int i = 0; i < 8; i++) {
        float acc = e[0]*v[0][i] + e[1]*v[1][i] + e[2]*v[2][i]
                  + e[3]*v[3][i] + e[4]*v[4][i];
        ob[(size_t)(cg*8+i)*HW] = acc * isum;
    }
}

extern "C" void kernel_launch(void* const* d_in, const int* in_sizes, int n_in,
                              void* d_out, int out_size)
{
    const float* x    = (const float*)d_in[0];
    const float* psm  = (const float*)d_in[1];
    // d_in[2] record_len, d_in[3] pairwise_t_matrix: unused by reference
    const float* traj = (const float*)d_in[4];
    const float* W1   = (const float*)d_in[5];
    const float* b1   = (const float*)d_in[6];
    const float* W2   = (const float*)d_in[7];
    const float* b2   = (const float*)d_in[8];
    const float* Wc1  = (const float*)d_in[9];
    const float* bc1  = (const float*)d_in[10];
    const float* Wc2  = (const float*)d_in[11];
    const float* bc2  = (const float*)d_in[12];
    float* out = (float*)d_out;

    k_prep<<<148, 128>>>(traj, W1, b1, W2, b2, Wc1);
    k_traj2<<<NN, 576>>>(bc1, Wc2, bc2);
    dim3 gm(WW/32, (HH+15)/16, NN);
    k_cmask<<<gm, 256>>>(psm);
    dim3 gf(HW/32, BB);
    k_fuse<<<gf, 256>>>(x, out);
}

// round 12
// speedup vs baseline: 3.1945x; 1.0342x over previous
#include <cuda_runtime.h>
#include <math.h>

#define BB 4
#define LL 5
#define TT 10
#define CC 64
#define HH 100
#define WW 352
#define NN (BB*LL)
#define HW (HH*WW)
#define H4 25
#define W4 88
#define P4 (H4*W4)

// PDL: let dependents launch early; wait = predecessor grid fully complete + visible
#define PDL_TRIGGER() asm volatile("griddepcontrol.launch_dependents;" ::: "memory")
#define PDL_WAIT()    asm volatile("griddepcontrol.wait;" ::: "memory")

// scratch (no allocations allowed)
__device__ float g_tm4[NN*P4];
__device__ float g_has[NN];
__device__ unsigned char g_mask[NN*HW];
__device__ float g_f[NN*128];
__device__ float g_R[9*128*64];       // conv weights pre-reduced to 9 border cases
__device__ int   g_xi[NN*TT], g_yi[NN*TT];

// fast sigmoid via tanh.approx (mask path only -- feeds a 0.01 threshold, never the output values)
__device__ __forceinline__ float fast_sigmoid(float xv) {
    float t;
    asm("tanh.approx.f32 %0, %1;" : "=f"(t) : "f"(xv*0.5f));
    return fmaf(t, 0.5f, 0.5f);
}

// 5x5 gaussian, sigma=1, scaled by 1/(2*pi*sigma)
__constant__ float c_G[25] = {
    0.0029150244947655228f, 0.013064233284684921f, 0.021539279301848634f, 0.013064233284684921f, 0.0029150244947655228f,
    0.013064233284684921f, 0.05854983152431917f, 0.09653235263005391f, 0.05854983152431917f, 0.013064233284684921f,
    0.021539279301848634f, 0.09653235263005391f, 0.15915494309189535f, 0.09653235263005391f, 0.021539279301848634f,
    0.013064233284684921f, 0.05854983152431917f, 0.09653235263005391f, 0.05854983152431917f, 0.013064233284684921f,
    0.0029150244947655228f, 0.013064233284684921f, 0.021539279301848634f, 0.013064233284684921f, 0.0029150244947655228f
};

// 7x7 splat table: exp(-(di^2+dj^2)/8), di,dj in [-3,3]
__constant__ float c_g7[49] = {
    0.10539922456186433f, 0.19689917292530676f, 0.2865047968601901f, 0.32465246735834974f, 0.2865047968601901f, 0.19689917292530676f, 0.10539922456186433f,
    0.19689917292530676f, 0.36787944117144233f, 0.5352614285189903f, 0.6065306597126334f, 0.5352614285189903f, 0.36787944117144233f, 0.19689917292530676f,
    0.2865047968601901f, 0.5352614285189903f, 0.7788007830714049f, 0.8824969025845955f, 0.7788007830714049f, 0.5352614285189903f, 0.2865047968601901f,
    0.32465246735834974f, 0.6065306597126334f, 0.8824969025845955f, 1.0f, 0.8824969025845955f, 0.6065306597126334f, 0.32465246735834974f,
    0.2865047968601901f, 0.5352614285189903f, 0.7788007830714049f, 0.8824969025845955f, 0.7788007830714049f, 0.5352614285189903f, 0.2865047968601901f,
    0.19689917292530676f, 0.36787944117144233f, 0.5352614285189903f, 0.6065306597126334f, 0.5352614285189903f, 0.36787944117144233f, 0.19689917292530676f,
    0.10539922456186433f, 0.19689917292530676f, 0.2865047968601901f, 0.32465246735834974f, 0.2865047968601901f, 0.19689917292530676f, 0.10539922456186433f
};

// ---------------- K1: prep. Blocks 0..127: reduce Wc1 -> R. Blocks 128..147: per-agent MLP ----------------
__global__ void __launch_bounds__(128)
k_prep(const float* __restrict__ traj_all,
       const float* __restrict__ W1, const float* __restrict__ b1,
       const float* __restrict__ W2, const float* __restrict__ b2,
       const float* __restrict__ Wc1)
{
    PDL_TRIGGER();
    int bid = blockIdx.x;
    int tid = threadIdx.x;

    if (bid < 128) {
        if (tid < 64) {
            int k = bid, o = tid;
            const float* w = Wc1 + (size_t)o*1152 + k*9;
            float w00=w[0], w01=w[1], w02=w[2];
            float w10=w[3], w11=w[4], w12=w[5];
            float w20=w[6], w21=w[7], w22=w[8];
            float rF0=w00+w01+w02, rL0=w01+w02, rR0=w00+w01;
            float rF1=w10+w11+w12, rL1=w11+w12, rR1=w10+w11;
            float rF2=w20+w21+w22, rL2=w21+w22, rR2=w20+w21;
            g_R[(0*128+k)*64+o]=rL1+rL2; g_R[(1*128+k)*64+o]=rF1+rF2; g_R[(2*128+k)*64+o]=rR1+rR2;
            g_R[(3*128+k)*64+o]=rL0+rL1+rL2; g_R[(4*128+k)*64+o]=rF0+rF1+rF2; g_R[(5*128+k)*64+o]=rR0+rR1+rR2;
            g_R[(6*128+k)*64+o]=rL0+rL1; g_R[(7*128+k)*64+o]=rF0+rF1; g_R[(8*128+k)*64+o]=rR0+rR1;
        }
        return;
    }

    int n = bid - 128;
    __shared__ float s_tr[TT*3];
    __shared__ float s_h[64];
    if (tid < TT*3) s_tr[tid] = traj_all[n*TT*3 + tid];
    __syncthreads();

    if (tid == 0) {
        int h = 0;
        for (int i = 0; i < TT*3; i++) if (s_tr[i] != 0.0f) h = 1;
        g_has[n] = (float)h;
    }
    if (tid < TT) {
        float px = s_tr[tid*3+0] / 0.4f;     // DISCRETE_RATIO
        float py = s_tr[tid*3+1] / 0.4f;
        int xi = (int)(px / 4.0f);           // truncation like .astype(int32)
        int yi = (int)(py / 4.0f);
        g_xi[n*TT+tid] = min(max(xi, 0), W4-1);
        g_yi[n*TT+tid] = min(max(yi, 0), H4-1);
    }
    if (tid < 64) {
        float acc = 0.0f;
        #pragma unroll
        for (int t = 0; t < TT; t++) {
            float z = b1[tid];
            z += s_tr[t*3+0]*W1[0*64+tid];
            z += s_tr[t*3+1]*W1[1*64+tid];
            z += s_tr[t*3+2]*W1[2*64+tid];
            acc += fmaxf(z, 0.0f);
        }
        s_h[tid] = acc * 0.1f;
    }
    __syncthreads();
    {
        float z = b2[tid];
        #pragma unroll 8
        for (int c = 0; c < 64; c++) z += s_h[c]*W2[c*128+tid];
        g_f[n*128+tid] = z;
    }
}

// ---------------- K2: per-agent attention(9 cases) + table splat + normalize ----------------
__global__ void __launch_bounds__(576)
k_traj2(const float* __restrict__ bc1, const float* __restrict__ Wc2,
        const float* __restrict__ bc2)
{
    PDL_TRIGGER();
    int n = blockIdx.x;
    int tid = threadIdx.x;
    __shared__ float s_f[128];
    __shared__ float s_a9[9];
    __shared__ float s_red[9][2];
    __shared__ int   s_xi[TT], s_yi[TT];
    __shared__ float s_g7[49];
    __shared__ float s_m[P4];
    __shared__ float s_wsum[18];

    if (tid >= 128 && tid < 128+49) s_g7[tid-128] = c_g7[tid-128];  // independent prelude
    PDL_WAIT();   // g_f/g_xi/g_R ready
    if (tid < 128) s_f[tid] = g_f[n*128+tid];
    if (tid < TT) { s_xi[tid] = g_xi[n*TT+tid]; s_yi[tid] = g_yi[n*TT+tid]; }
    __syncthreads();

    {
        int q = tid / 64, o = tid & 63;
        float acc = bc1[o];
        const float* Rp = g_R + (size_t)q*128*64 + o;
        #pragma unroll 8
        for (int k = 0; k < 128; k++) acc += s_f[k] * Rp[(size_t)k*64];
        float t = Wc2[o] * fmaxf(acc, 0.0f);
        #pragma unroll
        for (int off = 16; off > 0; off >>= 1)
            t += __shfl_down_sync(0xFFFFFFFFu, t, off);
        if ((tid & 31) == 0) s_red[q][(tid >> 5) & 1] = t;
    }
    __syncthreads();
    if (tid < 9) {
        float z = bc2[0] + s_red[tid][0] + s_red[tid][1];
        s_a9[tid] = fast_sigmoid(z);
    }
    __syncthreads();

    float lsum = 0.0f;
    for (int p = tid; p < P4; p += 576) {
        int i = p / W4, j = p - (p / W4)*W4;
        float m = 0.0f;
        #pragma unroll
        for (int t = 0; t < TT; t++) {
            int di = i - s_yi[t] + 3, dj = j - s_xi[t] + 3;
            if ((unsigned)di < 7u && (unsigned)dj < 7u) m += s_g7[di*7+dj];
        }
        s_m[p] = m; lsum += m;
    }
    #pragma unroll
    for (int off = 16; off > 0; off >>= 1)
        lsum += __shfl_down_sync(0xFFFFFFFFu, lsum, off);
    if ((tid & 31) == 0) s_wsum[tid >> 5] = lsum;
    __syncthreads();
    if (tid == 0) {
        float t = 0.0f;
        #pragma unroll
        for (int w = 0; w < 18; w++) t += s_wsum[w];
        s_wsum[0] = 1.0f / fmaxf(t, 1e-12f);
    }
    __syncthreads();
    float inv = s_wsum[0];
    for (int p = tid; p < P4; p += 576) {
        int i = p / W4, j = p - (p / W4)*W4;
        int r  = (i == 0) ? 0 : ((i == H4-1) ? 2 : 1);
        int cc = (j == 0) ? 0 : ((j == W4-1) ? 2 : 1);
        g_tm4[n*P4 + p] = s_m[p]*inv*s_a9[r*3+cc];
    }
}

// ---------------- K3: fused cmap + 5x5 smooth + threshold + ego force ----------------
// Tile 32x16, halo 2 -> 36x20 cmap values in smem (zero outside = conv zero-pad).
__global__ void __launch_bounds__(256)
k_cmask(const float* __restrict__ psm)
{
    PDL_TRIGGER();
    __shared__ float s_c[20][36];
    int n  = blockIdx.z;
    int bx = blockIdx.x * 32;
    int by = blockIdx.y * 16;
    int tid = threadIdx.x;

    PDL_WAIT();   // g_tm4/g_has ready
    const float* tmn = g_tm4 + n*P4;
    float has = g_has[n];

    for (int i = tid; i < 20*36; i += 256) {
        int ly = i / 36, lx = i - ly*36;
        int gx = bx + lx - 2, gy = by + ly - 2;
        float val = 0.0f;
        if (gx >= 0 && gx < WW && gy >= 0 && gy < HH) {
            float uy = fminf(fmaxf((gy+0.5f)*0.25f - 0.5f, 0.0f), (float)(H4-1));
            float ux = fminf(fmaxf((gx+0.5f)*0.25f - 0.5f, 0.0f), (float)(W4-1));
            int y0 = (int)uy, x0 = (int)ux;
            float fy = uy - y0, fx = ux - x0;
            int y1 = min(y0+1, H4-1), x1 = min(x0+1, W4-1);
            float v00 = tmn[y0*W4+x0], v01 = tmn[y0*W4+x1];
            float v10 = tmn[y1*W4+x0], v11 = tmn[y1*W4+x1];
            float tm = v00*(1.0f-fy)*(1.0f-fx) + v01*(1.0f-fy)*fx
                     + v10*fy*(1.0f-fx)        + v11*fy*fx;
            float fac = 1.0f + has*tm;
            int p = gy*WW + gx;
            float c0 = fast_sigmoid(psm[(size_t)(n*2+0)*HW + p]*fac);
            float c1 = fast_sigmoid(psm[(size_t)(n*2+1)*HW + p]*fac);
            val = fmaxf(c0, c1);
        }
        s_c[ly][lx] = val;
    }
    __syncthreads();

    int lx = tid & 31;
    int l  = n % LL;
    unsigned char* mb = g_mask + (size_t)n*HW;
    #pragma unroll
    for (int r = 0; r < 2; r++) {
        int ly = (tid >> 5) + r*8;
        int gx = bx + lx, gy = by + ly;
        if (gy < HH) {
            float acc = 0.0f;
            #pragma unroll
            for (int dy = 0; dy < 5; dy++) {
                #pragma unroll
                for (int dx = 0; dx < 5; dx++)
                    acc += c_G[dy*5+dx] * s_c[ly+dy][lx+dx];
            }
            mb[gy*WW + gx] = (l == 0) ? 1 : ((acc > 0.01f) ? 1 : 0);
        }
    }
}

// ---------------- K4: masked ego-row attention fusion (PDL two-phase) ----------------
// Phase 1 (no mask needed): load x raw, compute raw ego dots. Masks are 0/1 and ego
// mask==1, so masked dot = mk[m] * raw dot. Phase 2 after griddepcontrol.wait.
__global__ void __launch_bounds__(256)
k_fuse(const float* __restrict__ x, float* __restrict__ out)
{
    __shared__ float s_d[8][5][32];

    int px = threadIdx.x & 31;
    int cg = threadIdx.x >> 5;        // 0..7
    int p  = blockIdx.x * 32 + px;    // HW = 35200 = 1100 * 32
    int b  = blockIdx.y;

    const float* xb = x + (size_t)b*LL*CC*HW + p;

    // ---- phase 1: raw loads + raw dots (overlaps the mask-producing chain) ----
    float v[LL][8];
    #pragma unroll
    for (int m = 0; m < LL; m++) {
        #pragma unroll
        for (int i = 0; i < 8; i++)
            v[m][i] = xb[(size_t)(m*CC + cg*8 + i)*HW];
    }

    float d[LL];
    #pragma unroll
    for (int m = 0; m < LL; m++) d[m] = 0.0f;
    #pragma unroll
    for (int i = 0; i < 8; i++) {
        #pragma unroll
        for (int m = 0; m < LL; m++) d[m] += v[0][i]*v[m][i];
    }
    #pragma unroll
    for (int m = 0; m < LL; m++) s_d[cg][m][px] = d[m];
    __syncthreads();

    // ---- phase 2: need the mask now ----
    PDL_WAIT();
    float mk[LL];
    #pragma unroll
    for (int m = 0; m < LL; m++)
        mk[m] = (float)g_mask[(size_t)(b*LL+m)*HW + p];

    // every thread reduces the 8 partials itself and computes softmax (no 2nd barrier)
    float e[LL], sum = 0.0f;
    #pragma unroll
    for (int m = 0; m < LL; m++) {
        float acc = 0.0f;
        #pragma unroll
        for (int g = 0; g < 8; g++) acc += s_d[g][m][px];
        e[m] = __expf(acc * mk[m] * 0.125f);   // mk in {0,1}, mk[0]==1; bounded exponent
        sum += e[m];
    }
    float isum = 1.0f/sum;

    float* ob = out + (size_t)b*CC*HW + p;
    #pragma unroll
    for (int i = 0; i < 8; i++) {
        float acc = e[0]*v[0][i]*mk[0] + e[1]*v[1][i]*mk[1] + e[2]*v[2][i]*mk[2]
                  + e[3]*v[3][i]*mk[3] + e[4]*v[4][i]*mk[4];
        ob[(size_t)(cg*8+i)*HW] = acc * isum;
    }
}

static void launch_pdl(cudaLaunchConfig_t cfg, cudaLaunchAttribute* attr)
{
    (void)cfg; (void)attr;
}

extern "C" void kernel_launch(void* const* d_in, const int* in_sizes, int n_in,
                              void* d_out, int out_size)
{
    const float* x    = (const float*)d_in[0];
    const float* psm  = (const float*)d_in[1];
    // d_in[2] record_len, d_in[3] pairwise_t_matrix: unused by reference
    const float* traj = (const float*)d_in[4];
    const float* W1   = (const float*)d_in[5];
    const float* b1   = (const float*)d_in[6];
    const float* W2   = (const float*)d_in[7];
    const float* b2   = (const float*)d_in[8];
    const float* Wc1  = (const float*)d_in[9];
    const float* bc1  = (const float*)d_in[10];
    const float* Wc2  = (const float*)d_in[11];
    const float* bc2  = (const float*)d_in[12];
    float* out = (float*)d_out;

    cudaLaunchAttribute pdl_attr[1];
    pdl_attr[0].id = cudaLaunchAttributeProgrammaticStreamSerialization;
    pdl_attr[0].val.programmaticStreamSerializationAllowed = 1;

    // K1 (no predecessor)
    k_prep<<<148, 128>>>(traj, W1, b1, W2, b2, Wc1);

    // K2 with PDL on K1
    {
        cudaLaunchConfig_t cfg = {};
        cfg.gridDim = dim3(NN, 1, 1); cfg.blockDim = dim3(576, 1, 1);
        cfg.dynamicSmemBytes = 0; cfg.stream = 0;
        cfg.attrs = pdl_attr; cfg.numAttrs = 1;
        cudaLaunchKernelEx(&cfg, k_traj2, bc1, Wc2, bc2);
    }
    // K3 with PDL on K2
    {
        cudaLaunchConfig_t cfg = {};
        cfg.gridDim = dim3(WW/32, (HH+15)/16, NN); cfg.blockDim = dim3(256, 1, 1);
        cfg.dynamicSmemBytes = 0; cfg.stream = 0;
        cfg.attrs = pdl_attr; cfg.numAttrs = 1;
        cudaLaunchKernelEx(&cfg, k_cmask, psm);
    }
    // K4 with PDL on K3: big x-load phase overlaps the whole mask chain
    {
        cudaLaunchConfig_t cfg = {};
        cfg.gridDim = dim3(HW/32, BB, 1); cfg.blockDim = dim3(256, 1, 1);
        cfg.dynamicSmemBytes = 0; cfg.stream = 0;
        cfg.attrs = pdl_attr; cfg.numAttrs = 1;
        cudaLaunchKernelEx(&cfg, k_fuse, x, out);
    }
}